// round 1
// baseline (speedup 1.0000x reference)
#include <cuda_runtime.h>
#include <math.h>
#include <stdint.h>

// ---------------- dims ----------------
#define B_IMG 64
#define R_REG 36
#define E_DIM 1024
#define C_CAP 64
#define L_W   32
#define N_DEP 30
#define NBLK  32
#define BLK   32
#define HID   512
#define LAM   9.0f

// ---------------- scratch (__device__ globals; no allocation) ----------------
__device__ float g_attn[(size_t)B_IMG * R_REG * C_CAP * L_W];   // (2304, 2048) logits = images @ caps^T
__device__ float g_scap[C_CAP * L_W];                           // per-caption graph scalar s[l]
__device__ float g_x[(size_t)C_CAP * B_IMG * L_W * NBLK];       // x = tnode * s
__device__ float g_w[B_IMG * C_CAP];                            // softmax weights over captions
__device__ float g_Wmu[HID * NBLK];                             // W_mu @ W_gc
__device__ float g_Wlv[HID * NBLK];                             // W_lv @ W_gc
__device__ float g_W1c[HID * NBLK];                             // W1   @ W_gc

// ---------------- kernel: compose W @ W_gc (512x512 @ 512x32) ----------------
__global__ void k_compose(const float* __restrict__ Wgc,
                          const float* __restrict__ Wmu,
                          const float* __restrict__ Wlv,
                          const float* __restrict__ W1) {
    int h = blockIdx.x;          // 0..511
    int m = blockIdx.y;          // 0..2
    int k = threadIdx.x;         // 0..31
    const float* W = (m == 0) ? Wmu : (m == 1) ? Wlv : W1;
    float acc = 0.f;
    #pragma unroll 8
    for (int j = 0; j < HID; j++)
        acc += W[h * HID + j] * Wgc[j * NBLK + k];
    float* dst = (m == 0) ? g_Wmu : (m == 1) ? g_Wlv : g_W1c;
    dst[h * NBLK + k] = acc;
}

// ---------------- kernel A: per-caption words_sim, adj, s[l] ----------------
// smem: caps (32 x 1025) + G(1024) + adj(1024)
#define A_SMEM_FLOATS (32 * 1025 + 1024 + 1024)
__global__ void k_caption(const float* __restrict__ caps,
                          const int* __restrict__ deps) {
    int c = blockIdx.x;
    int t = threadIdx.x;  // 256 threads
    extern __shared__ float sh[];
    float* cs  = sh;                  // [32][1025]
    float* G   = cs + 32 * 1025;      // [32][32] gram -> softmax rows
    float* adj = G + 1024;            // [32][32]

    const float* cp = caps + (size_t)c * L_W * E_DIM;
    for (int i = t; i < L_W * E_DIM; i += 256) {
        int l = i >> 10, e = i & 1023;
        cs[l * 1025 + e] = cp[i];
    }
    __syncthreads();

    for (int p = t; p < 1024; p += 256) {
        int i = p >> 5, j = p & 31;
        float acc = 0.f;
        #pragma unroll 8
        for (int e = 0; e < E_DIM; e++)
            acc += cs[i * 1025 + e] * cs[j * 1025 + e];
        G[p] = acc;
    }
    __syncthreads();

    if (t < 32) {
        float m = -1e30f;
        for (int j = 0; j < 32; j++) m = fmaxf(m, G[t * 32 + j]);
        float s = 0.f;
        for (int j = 0; j < 32; j++) {
            float e = expf(LAM * (G[t * 32 + j] - m));
            G[t * 32 + j] = e;
            s += e;
        }
        float inv = 1.f / s;
        for (int j = 0; j < 32; j++) G[t * 32 + j] *= inv;
    }
    for (int p = t; p < 1024; p += 256) adj[p] = 0.f;
    __syncthreads();
    if (t == 0) {
        // build_sparse_graph: skip pair 0, symmetric 0/1 scatter, then +I
        for (int i = 1; i < N_DEP; i++) {
            int a = deps[c * (N_DEP * 2) + i * 2 + 0];
            int b = deps[c * (N_DEP * 2) + i * 2 + 1];
            adj[a * 32 + b] = 1.f;
            adj[b * 32 + a] = 1.f;
        }
        for (int i = 0; i < 32; i++) adj[i * 32 + i] += 1.f;
    }
    __syncthreads();
    if (t < 32) {
        float ss = 0.f;
        for (int j = 0; j < 32; j++) {
            float m2 = adj[t * 32 + j] * G[t * 32 + j];
            ss += m2 * m2;
        }
        float inv = 1.f / (sqrtf(ss) + 1e-8f);
        float s = 0.f;
        for (int j = 0; j < 32; j++) {
            float a = adj[t * 32 + j];
            s += a * G[t * 32 + j] * inv * a;
        }
        g_scap[c * 32 + t] = s;
    }
}

// ---------------- kernel B: logits GEMM  C = A(2304,1024) @ B(2048,1024)^T ----------------
__global__ void k_gemm_nt(const float* __restrict__ A,
                          const float* __restrict__ B,
                          float* __restrict__ C) {
    const int M = B_IMG * R_REG;   // 2304
    const int N = C_CAP * L_W;     // 2048
    const int K = E_DIM;           // 1024
    __shared__ float As[16][68];
    __shared__ float Bs[16][68];
    int tm = blockIdx.y, tn = blockIdx.x;
    int t = threadIdx.x;           // 256
    int tx = t & 15, ty = t >> 4;
    int arow = t >> 2;             // 0..63
    int acol4 = (t & 3) * 4;       // 0,4,8,12
    float acc[4][4];
    #pragma unroll
    for (int i = 0; i < 4; i++)
        #pragma unroll
        for (int j = 0; j < 4; j++) acc[i][j] = 0.f;

    for (int k0 = 0; k0 < K; k0 += 16) {
        float4 av = *(const float4*)(A + (size_t)(tm * 64 + arow) * K + k0 + acol4);
        As[acol4 + 0][arow] = av.x;
        As[acol4 + 1][arow] = av.y;
        As[acol4 + 2][arow] = av.z;
        As[acol4 + 3][arow] = av.w;
        float4 bv = *(const float4*)(B + (size_t)(tn * 64 + arow) * K + k0 + acol4);
        Bs[acol4 + 0][arow] = bv.x;
        Bs[acol4 + 1][arow] = bv.y;
        Bs[acol4 + 2][arow] = bv.z;
        Bs[acol4 + 3][arow] = bv.w;
        __syncthreads();
        #pragma unroll
        for (int k = 0; k < 16; k++) {
            float4 af = *(const float4*)&As[k][ty * 4];
            float4 bf = *(const float4*)&Bs[k][tx * 4];
            float a_[4] = {af.x, af.y, af.z, af.w};
            float b_[4] = {bf.x, bf.y, bf.z, bf.w};
            #pragma unroll
            for (int i = 0; i < 4; i++)
                #pragma unroll
                for (int j = 0; j < 4; j++)
                    acc[i][j] += a_[i] * b_[j];
        }
        __syncthreads();
    }
    #pragma unroll
    for (int i = 0; i < 4; i++) {
        int row = tm * 64 + ty * 4 + i;
        float4 v = make_float4(acc[i][0], acc[i][1], acc[i][2], acc[i][3]);
        *(float4*)(C + (size_t)row * N + tn * 64 + tx * 4) = v;
    }
}

// ---------------- kernel C: fused per-(c,b): attn -> wctx -> tnode -> x -> sim ----------------
// smem: wctx[32*1024] + tnorm[32*36] + wlr[32*36] + xs[1024] + red[32]
#define C_SMEM_FLOATS (32 * 1024 + 32 * 36 + 32 * 36 + 1024 + 32)
__global__ void k_fused(const float* __restrict__ imgs,
                        const float* __restrict__ caps,
                        const float* __restrict__ b1,
                        const float* __restrict__ W2,
                        const float* __restrict__ b2,
                        float* __restrict__ out_sim) {
    int c = blockIdx.x;
    int b = blockIdx.y;
    int t = threadIdx.x;  // 512
    extern __shared__ float sh[];
    float* wctx  = sh;                       // [32][1024]
    float* tnorm = wctx + 32 * 1024;         // [l][r]
    float* wlr   = tnorm + 32 * 36;          // [l][r]
    float* xs    = wlr + 32 * 36;            // [32][32]
    float* red   = xs + 1024;                // 16 partials

    // phase 1: read logits, LeakyReLU(0.1), l2norm over words per region
    if (t < R_REG) {
        float v[32];
        float ss = 0.f;
        const float* arow = g_attn + ((size_t)(b * R_REG + t)) * (C_CAP * L_W) + c * L_W;
        #pragma unroll
        for (int j = 0; j < 32; j++) {
            float a = arow[j];
            a = (a >= 0.f) ? a : 0.1f * a;
            v[j] = a;
            ss += a * a;
        }
        float inv = 1.f / (sqrtf(ss) + 1e-8f);
        #pragma unroll
        for (int j = 0; j < 32; j++) tnorm[j * R_REG + t] = v[j] * inv;
    }
    __syncthreads();
    // softmax over regions per word (with lambda)
    if (t < L_W) {
        float m = -1e30f;
        #pragma unroll
        for (int r = 0; r < R_REG; r++) m = fmaxf(m, tnorm[t * R_REG + r]);
        float s = 0.f;
        float e[R_REG];
        #pragma unroll
        for (int r = 0; r < R_REG; r++) {
            e[r] = expf(LAM * (tnorm[t * R_REG + r] - m));
            s += e[r];
        }
        float inv = 1.f / s;
        #pragma unroll
        for (int r = 0; r < R_REG; r++) wlr[t * R_REG + r] = e[r] * inv;
    }
    __syncthreads();

    // phase 2: wctx[l][e] = sum_r wlr[l][r] * images[b][r][e]
    const float* imgb = imgs + (size_t)b * R_REG * E_DIM;
    #pragma unroll
    for (int half = 0; half < 2; half++) {
        int e = t + half * 512;
        float col[R_REG];
        #pragma unroll
        for (int r = 0; r < R_REG; r++) col[r] = imgb[r * E_DIM + e];
        #pragma unroll 4
        for (int l = 0; l < L_W; l++) {
            float acc = 0.f;
            #pragma unroll
            for (int r = 0; r < R_REG; r++) acc += wlr[l * R_REG + r] * col[r];
            wctx[l * E_DIM + e] = acc;
        }
    }
    __syncthreads();

    // phase 3: blockwise cosine tnode, scale by s[l], write x
    const float* capc = caps + (size_t)c * L_W * E_DIM;
    float* xout = g_x + (size_t)(c * B_IMG + b) * (L_W * NBLK);
    #pragma unroll
    for (int p = t; p < L_W * NBLK; p += 512) {
        int l = p >> 5, k = p & 31;
        float num = 0.f, qn = 0.f, cn = 0.f;
        const float* q = capc + l * E_DIM + k * BLK;
        const float* w = wctx + l * E_DIM + k * BLK;
        #pragma unroll
        for (int j = 0; j < BLK; j++) {
            float a = q[j], bb = w[j];
            num += a * bb;
            qn += a * a;
            cn += bb * bb;
        }
        float den = fmaxf(sqrtf(qn) * sqrtf(cn), 1e-8f);
        float x = (num / den) * g_scap[c * 32 + l];
        xs[p] = x;
        xout[p] = x;
    }
    __syncthreads();

    // phase 4: sim = mean_l( tanh(x @ W1c^T + b1) @ W2 ) + b2
    float w1r[NBLK];
    #pragma unroll
    for (int k = 0; k < NBLK; k++) w1r[k] = g_W1c[t * NBLK + k];
    float bb1 = b1[t];
    float w2 = W2[t];
    float acc = 0.f;
    #pragma unroll 4
    for (int l = 0; l < L_W; l++) {
        float d = bb1;
        #pragma unroll
        for (int k = 0; k < NBLK; k++) d += xs[l * NBLK + k] * w1r[k];
        acc += tanhf(d) * w2;
    }
    #pragma unroll
    for (int o = 16; o; o >>= 1) acc += __shfl_down_sync(0xffffffffu, acc, o);
    if ((t & 31) == 0) red[t >> 5] = acc;
    __syncthreads();
    if (t == 0) {
        float s = 0.f;
        #pragma unroll
        for (int i = 0; i < 16; i++) s += red[i];
        out_sim[b * C_CAP + c] = s * (1.f / 32.f) + b2[0];
    }
}

// ---------------- kernel D: softmax over captions per image ----------------
__global__ void k_softmax(const float* __restrict__ sims) {
    int b = blockIdx.x;
    int t = threadIdx.x;  // 64
    __shared__ float sh[64];
    __shared__ float mx, sm;
    float v = sims[b * C_CAP + t];
    sh[t] = v;
    __syncthreads();
    if (t == 0) {
        float m = sh[0];
        for (int i = 1; i < 64; i++) m = fmaxf(m, sh[i]);
        mx = m;
    }
    __syncthreads();
    float e = expf(v - mx);
    sh[t] = e;
    __syncthreads();
    if (t == 0) {
        float s = 0.f;
        for (int i = 0; i < 64; i++) s += sh[i];
        sm = s;
    }
    __syncthreads();
    g_w[b * C_CAP + t] = e / sm;
}

// ---------------- kernel E: weighted Gaussian moments ----------------
__global__ void k_moments(const float* __restrict__ bmu,
                          const float* __restrict__ blv,
                          float* __restrict__ out) {
    int bl = blockIdx.x;        // 0..2047  (b*32 + l)
    int b = bl >> 5, l = bl & 31;
    int t = threadIdx.x;        // 512 (h)
    __shared__ float xsh[C_CAP * NBLK];  // [c][k]
    __shared__ float wsh[C_CAP];
    #pragma unroll
    for (int i = t; i < C_CAP * NBLK; i += 512) {
        int c = i >> 5, k = i & 31;
        xsh[i] = g_x[(size_t)(c * B_IMG + b) * (L_W * NBLK) + l * NBLK + k];
    }
    if (t < C_CAP) wsh[t] = g_w[b * C_CAP + t];
    __syncthreads();

    float wm[NBLK], wl[NBLK];
    #pragma unroll
    for (int k = 0; k < NBLK; k++) {
        wm[k] = g_Wmu[t * NBLK + k];
        wl[k] = g_Wlv[t * NBLK + k];
    }
    float bm = bmu[t], bv = blv[t];
    float am = 0.f, ae = 0.f;
    #pragma unroll 2
    for (int c = 0; c < C_CAP; c++) {
        float dm = bm, dl = bv;
        const float* xr = xsh + c * NBLK;
        #pragma unroll
        for (int k = 0; k < NBLK; k++) {
            dm += xr[k] * wm[k];
            dl += xr[k] * wl[k];
        }
        float w = wsh[c];
        am += w * dm;
        ae += w * (expf(dl) + dm * dm);
    }
    float var = ae - am * am;
    float sg = sqrtf(fmaxf(var, 1e-8f));
    size_t o = (size_t)bl * HID + t;
    out[4096 + o] = am;                              // mu_word
    out[4096 + (size_t)B_IMG * L_W * HID + o] = sg;  // sigma_word
}

// ---------------- launch ----------------
extern "C" void kernel_launch(void* const* d_in, const int* in_sizes, int n_in,
                              void* d_out, int out_size) {
    const float* images   = (const float*)d_in[0];
    const float* captions = (const float*)d_in[1];
    const int*   depends  = (const int*)d_in[2];
    const float* W_gc     = (const float*)d_in[3];
    const float* W_mu     = (const float*)d_in[4];
    const float* b_mu     = (const float*)d_in[5];
    const float* W_lv     = (const float*)d_in[6];
    const float* b_lv     = (const float*)d_in[7];
    const float* W1       = (const float*)d_in[8];
    const float* b1       = (const float*)d_in[9];
    const float* W2       = (const float*)d_in[10];
    const float* b2       = (const float*)d_in[11];
    float* out = (float*)d_out;

    static bool attr_set = false;
    if (!attr_set) {
        cudaFuncSetAttribute(k_caption, cudaFuncAttributeMaxDynamicSharedMemorySize,
                             A_SMEM_FLOATS * sizeof(float));
        cudaFuncSetAttribute(k_fused, cudaFuncAttributeMaxDynamicSharedMemorySize,
                             C_SMEM_FLOATS * sizeof(float));
        attr_set = true;
    }

    float* attn_ptr;
    cudaGetSymbolAddress((void**)&attn_ptr, g_attn);

    // 1) composed 512x32 weight matrices
    k_compose<<<dim3(HID, 3), 32>>>(W_gc, W_mu, W_lv, W1);
    // 2) per-caption graph scalar s[l]
    k_caption<<<C_CAP, 256, A_SMEM_FLOATS * sizeof(float)>>>(captions, depends);
    // 3) logits GEMM (2304 x 2048 x 1024)
    k_gemm_nt<<<dim3(32, 36), 256>>>(images, captions, attn_ptr);
    // 4) fused attention / wctx / tnode / sim per (caption, image)
    k_fused<<<dim3(C_CAP, B_IMG), 512, C_SMEM_FLOATS * sizeof(float)>>>(
        images, captions, b1, W2, b2, out);
    // 5) softmax over captions
    k_softmax<<<B_IMG, 64>>>(out);
    // 6) weighted Gaussian moments -> mu_word, sigma_word
    k_moments<<<B_IMG * L_W, HID>>>(b_mu, b_lv, out);
}

// round 2
// speedup vs baseline: 1.1699x; 1.1699x over previous
#include <cuda_runtime.h>
#include <math.h>
#include <stdint.h>

// ---------------- dims ----------------
#define B_IMG 64
#define R_REG 36
#define E_DIM 1024
#define C_CAP 64
#define L_W   32
#define N_DEP 30
#define NBLK  32
#define BLK   32
#define HID   512
#define LAM   9.0f

// ---------------- scratch (__device__ globals; no allocation) ----------------
__device__ float g_attn[(size_t)B_IMG * R_REG * C_CAP * L_W];   // (2304, 2048) logits
__device__ float g_scap[C_CAP * L_W];                           // per-caption graph scalar s[l]
__device__ float g_x[(size_t)C_CAP * B_IMG * L_W * NBLK];       // x = tnode * s
__device__ float g_w[B_IMG * C_CAP];                            // softmax weights over captions
__device__ float g_Wmu[HID * NBLK];                             // W_mu @ W_gc
__device__ float g_Wlv[HID * NBLK];                             // W_lv @ W_gc
__device__ float g_W1c[HID * NBLK];                             // W1   @ W_gc

// ---------------- kernel: compose W @ W_gc (512x512 @ 512x32) ----------------
__global__ void k_compose(const float* __restrict__ Wgc,
                          const float* __restrict__ Wmu,
                          const float* __restrict__ Wlv,
                          const float* __restrict__ W1) {
    int h = blockIdx.x;          // 0..511
    int m = blockIdx.y;          // 0..2
    int k = threadIdx.x;         // 0..31
    const float* W = (m == 0) ? Wmu : (m == 1) ? Wlv : W1;
    float acc = 0.f;
    #pragma unroll 8
    for (int j = 0; j < HID; j++)
        acc += W[h * HID + j] * Wgc[j * NBLK + k];
    float* dst = (m == 0) ? g_Wmu : (m == 1) ? g_Wlv : g_W1c;
    dst[h * NBLK + k] = acc;
}

// ---------------- kernel A: per-caption words_sim, adj, s[l] ----------------
#define A_SMEM_FLOATS (32 * 1025 + 1024 + 1024)
__global__ void k_caption(const float* __restrict__ caps,
                          const int* __restrict__ deps) {
    int c = blockIdx.x;
    int t = threadIdx.x;  // 256 threads
    extern __shared__ float sh[];
    float* cs  = sh;                  // [32][1025]
    float* G   = cs + 32 * 1025;      // [32][32] gram -> softmax rows
    float* adj = G + 1024;            // [32][32]

    const float* cp = caps + (size_t)c * L_W * E_DIM;
    for (int i = t; i < L_W * E_DIM; i += 256) {
        int l = i >> 10, e = i & 1023;
        cs[l * 1025 + e] = cp[i];
    }
    __syncthreads();

    for (int p = t; p < 1024; p += 256) {
        int i = p >> 5, j = p & 31;
        float acc = 0.f;
        #pragma unroll 8
        for (int e = 0; e < E_DIM; e++)
            acc += cs[i * 1025 + e] * cs[j * 1025 + e];
        G[p] = acc;
    }
    __syncthreads();

    if (t < 32) {
        float m = -1e30f;
        for (int j = 0; j < 32; j++) m = fmaxf(m, G[t * 32 + j]);
        float s = 0.f;
        for (int j = 0; j < 32; j++) {
            float e = expf(LAM * (G[t * 32 + j] - m));
            G[t * 32 + j] = e;
            s += e;
        }
        float inv = 1.f / s;
        for (int j = 0; j < 32; j++) G[t * 32 + j] *= inv;
    }
    for (int p = t; p < 1024; p += 256) adj[p] = 0.f;
    __syncthreads();
    if (t == 0) {
        for (int i = 1; i < N_DEP; i++) {
            int a = deps[c * (N_DEP * 2) + i * 2 + 0];
            int b = deps[c * (N_DEP * 2) + i * 2 + 1];
            adj[a * 32 + b] = 1.f;
            adj[b * 32 + a] = 1.f;
        }
        for (int i = 0; i < 32; i++) adj[i * 32 + i] += 1.f;
    }
    __syncthreads();
    if (t < 32) {
        float ss = 0.f;
        for (int j = 0; j < 32; j++) {
            float m2 = adj[t * 32 + j] * G[t * 32 + j];
            ss += m2 * m2;
        }
        float inv = 1.f / (sqrtf(ss) + 1e-8f);
        float s = 0.f;
        for (int j = 0; j < 32; j++) {
            float a = adj[t * 32 + j];
            s += a * G[t * 32 + j] * inv * a;
        }
        g_scap[c * 32 + t] = s;
    }
}

// ---------------- kernel B: logits GEMM  C = A(2304,1024) @ B(2048,1024)^T ----------------
// 128x128 tile, 8x8 micro-tile, BK=8
__global__ void __launch_bounds__(256) k_gemm_nt(const float* __restrict__ A,
                                                 const float* __restrict__ B,
                                                 float* __restrict__ C) {
    __shared__ float As[8][132];
    __shared__ float Bs[8][132];
    int tm = blockIdx.y, tn = blockIdx.x;
    int t = threadIdx.x;           // 256
    int ty = t >> 4, tx = t & 15;  // 16 x 16
    int lr = t >> 1;               // 0..127 load row
    int lk = (t & 1) * 4;          // 0 or 4
    const float* Ab = A + (size_t)(tm * 128 + lr) * E_DIM + lk;
    const float* Bb = B + (size_t)(tn * 128 + lr) * E_DIM + lk;
    float acc[8][8];
    #pragma unroll
    for (int i = 0; i < 8; i++)
        #pragma unroll
        for (int j = 0; j < 8; j++) acc[i][j] = 0.f;

    for (int k0 = 0; k0 < E_DIM; k0 += 8) {
        float4 av = *(const float4*)(Ab + k0);
        float4 bv = *(const float4*)(Bb + k0);
        __syncthreads();
        As[lk + 0][lr] = av.x; As[lk + 1][lr] = av.y;
        As[lk + 2][lr] = av.z; As[lk + 3][lr] = av.w;
        Bs[lk + 0][lr] = bv.x; Bs[lk + 1][lr] = bv.y;
        Bs[lk + 2][lr] = bv.z; Bs[lk + 3][lr] = bv.w;
        __syncthreads();
        #pragma unroll
        for (int k = 0; k < 8; k++) {
            float4 a0 = *(const float4*)&As[k][ty * 4];
            float4 a1 = *(const float4*)&As[k][64 + ty * 4];
            float4 b0 = *(const float4*)&Bs[k][tx * 4];
            float4 b1 = *(const float4*)&Bs[k][64 + tx * 4];
            float a_[8] = {a0.x, a0.y, a0.z, a0.w, a1.x, a1.y, a1.z, a1.w};
            float b_[8] = {b0.x, b0.y, b0.z, b0.w, b1.x, b1.y, b1.z, b1.w};
            #pragma unroll
            for (int i = 0; i < 8; i++)
                #pragma unroll
                for (int j = 0; j < 8; j++)
                    acc[i][j] += a_[i] * b_[j];
        }
    }
    const int N = C_CAP * L_W;  // 2048
    #pragma unroll
    for (int i = 0; i < 8; i++) {
        int row = tm * 128 + ((i < 4) ? (ty * 4 + i) : (64 + ty * 4 + (i - 4)));
        float4 v0 = make_float4(acc[i][0], acc[i][1], acc[i][2], acc[i][3]);
        float4 v1 = make_float4(acc[i][4], acc[i][5], acc[i][6], acc[i][7]);
        *(float4*)(C + (size_t)row * N + tn * 128 + tx * 4) = v0;
        *(float4*)(C + (size_t)row * N + tn * 128 + 64 + tx * 4) = v1;
    }
}

// ---------------- kernel C: fused per-(c,b): attn -> wctx(reg) -> tnode -> x -> sim ----------------
// lane j owns element j of each 32-wide block; shfl_xor reduction; no wctx smem
__global__ void __launch_bounds__(512) k_fused(const float* __restrict__ imgs,
                                               const float* __restrict__ caps,
                                               const float* __restrict__ b1,
                                               const float* __restrict__ W2,
                                               const float* __restrict__ b2,
                                               float* __restrict__ out_sim) {
    int c = blockIdx.x;
    int b = blockIdx.y;
    int t = threadIdx.x;  // 512 = 16 warps
    __shared__ float tnorm[L_W * R_REG];
    __shared__ float wlr[L_W * R_REG];
    __shared__ float xs[L_W * NBLK];
    __shared__ float ssc[L_W];
    __shared__ float red[16];

    // phase 1: logits -> LeakyReLU -> l2norm over words (per region)
    if (t < R_REG) {
        float v[L_W];
        float ss = 0.f;
        const float* arow = g_attn + ((size_t)(b * R_REG + t)) * (C_CAP * L_W) + c * L_W;
        #pragma unroll
        for (int j = 0; j < L_W; j++) {
            float a = arow[j];
            a = (a >= 0.f) ? a : 0.1f * a;
            v[j] = a;
            ss += a * a;
        }
        float inv = 1.f / (sqrtf(ss) + 1e-8f);
        #pragma unroll
        for (int j = 0; j < L_W; j++) tnorm[j * R_REG + t] = v[j] * inv;
    }
    if (t < L_W) ssc[t] = g_scap[c * L_W + t];
    __syncthreads();
    // softmax over regions per word (with lambda)
    if (t < L_W) {
        float m = -1e30f;
        #pragma unroll
        for (int r = 0; r < R_REG; r++) m = fmaxf(m, tnorm[t * R_REG + r]);
        float s = 0.f;
        float e[R_REG];
        #pragma unroll
        for (int r = 0; r < R_REG; r++) {
            e[r] = expf(LAM * (tnorm[t * R_REG + r] - m));
            s += e[r];
        }
        float inv = 1.f / s;
        #pragma unroll
        for (int r = 0; r < R_REG; r++) wlr[t * R_REG + r] = e[r] * inv;
    }
    __syncthreads();

    // phase 2+3 fused: per warp, 2 blocks (k0, k0+16); lane j = element j of block
    int warp = t >> 5, lane = t & 31;
    int e0 = warp * 32 + lane;
    int e1 = (warp + 16) * 32 + lane;
    const float* imgb = imgs + (size_t)b * R_REG * E_DIM;
    const float* capc = caps + (size_t)c * L_W * E_DIM;
    float col0[R_REG], col1[R_REG];
    #pragma unroll
    for (int r = 0; r < R_REG; r++) {
        col0[r] = imgb[r * E_DIM + e0];
        col1[r] = imgb[r * E_DIM + e1];
    }
    float* xout = g_x + (size_t)(c * B_IMG + b) * (L_W * NBLK);
    #pragma unroll 2
    for (int l = 0; l < L_W; l++) {
        float w0 = 0.f, w1 = 0.f;
        #pragma unroll
        for (int r = 0; r < R_REG; r++) {
            float wv = wlr[l * R_REG + r];
            w0 = fmaf(wv, col0[r], w0);
            w1 = fmaf(wv, col1[r], w1);
        }
        float q0 = capc[l * E_DIM + e0];
        float q1 = capc[l * E_DIM + e1];
        float n0 = q0 * w0, a0 = q0 * q0, c0 = w0 * w0;
        float n1 = q1 * w1, a1 = q1 * q1, c1 = w1 * w1;
        #pragma unroll
        for (int o = 16; o; o >>= 1) {
            n0 += __shfl_xor_sync(0xffffffffu, n0, o);
            a0 += __shfl_xor_sync(0xffffffffu, a0, o);
            c0 += __shfl_xor_sync(0xffffffffu, c0, o);
            n1 += __shfl_xor_sync(0xffffffffu, n1, o);
            a1 += __shfl_xor_sync(0xffffffffu, a1, o);
            c1 += __shfl_xor_sync(0xffffffffu, c1, o);
        }
        if (lane == 0) {
            float sc = ssc[l];
            float d0 = fmaxf(sqrtf(a0) * sqrtf(c0), 1e-8f);
            float d1 = fmaxf(sqrtf(a1) * sqrtf(c1), 1e-8f);
            float x0 = (n0 / d0) * sc;
            float x1 = (n1 / d1) * sc;
            xs[l * NBLK + warp] = x0;
            xs[l * NBLK + warp + 16] = x1;
            xout[l * NBLK + warp] = x0;
            xout[l * NBLK + warp + 16] = x1;
        }
    }
    __syncthreads();

    // phase 4: sim = mean_l( tanh(x @ W1c^T + b1) @ W2 ) + b2
    float w1r[NBLK];
    #pragma unroll
    for (int k = 0; k < NBLK; k++) w1r[k] = g_W1c[t * NBLK + k];
    float bb1 = b1[t];
    float w2 = W2[t];
    float acc = 0.f;
    #pragma unroll 4
    for (int l = 0; l < L_W; l++) {
        float d = bb1;
        #pragma unroll
        for (int k = 0; k < NBLK; k++) d += xs[l * NBLK + k] * w1r[k];
        acc += tanhf(d) * w2;
    }
    #pragma unroll
    for (int o = 16; o; o >>= 1) acc += __shfl_down_sync(0xffffffffu, acc, o);
    if (lane == 0) red[warp] = acc;
    __syncthreads();
    if (t == 0) {
        float s = 0.f;
        #pragma unroll
        for (int i = 0; i < 16; i++) s += red[i];
        out_sim[b * C_CAP + c] = s * (1.f / 32.f) + b2[0];
    }
}

// ---------------- kernel D: softmax over captions per image ----------------
__global__ void k_softmax(const float* __restrict__ sims) {
    int b = blockIdx.x;
    int t = threadIdx.x;  // 64
    __shared__ float sh[64];
    __shared__ float mx, sm;
    float v = sims[b * C_CAP + t];
    sh[t] = v;
    __syncthreads();
    if (t == 0) {
        float m = sh[0];
        for (int i = 1; i < 64; i++) m = fmaxf(m, sh[i]);
        mx = m;
    }
    __syncthreads();
    float e = expf(v - mx);
    sh[t] = e;
    __syncthreads();
    if (t == 0) {
        float s = 0.f;
        for (int i = 0; i < 64; i++) s += sh[i];
        sm = s;
    }
    __syncthreads();
    g_w[b * C_CAP + t] = e / sm;
}

// ---------------- kernel E: weighted Gaussian moments ----------------
__global__ void __launch_bounds__(512) k_moments(const float* __restrict__ bmu,
                                                 const float* __restrict__ blv,
                                                 float* __restrict__ out) {
    int bl = blockIdx.x;        // 0..2047  (b*32 + l)
    int b = bl >> 5, l = bl & 31;
    int t = threadIdx.x;        // 512 (h)
    __shared__ float xsh[C_CAP * NBLK];  // [c][k]
    __shared__ float wsh[C_CAP];
    #pragma unroll
    for (int i = t; i < C_CAP * NBLK; i += 512) {
        int c = i >> 5, k = i & 31;
        xsh[i] = g_x[(size_t)(c * B_IMG + b) * (L_W * NBLK) + l * NBLK + k];
    }
    if (t < C_CAP) wsh[t] = g_w[b * C_CAP + t];
    __syncthreads();

    float wm[NBLK], wl[NBLK];
    #pragma unroll
    for (int k = 0; k < NBLK; k++) {
        wm[k] = g_Wmu[t * NBLK + k];
        wl[k] = g_Wlv[t * NBLK + k];
    }
    float bm = bmu[t], bv = blv[t];
    float am = 0.f, ae = 0.f;
    #pragma unroll 2
    for (int c = 0; c < C_CAP; c++) {
        float dm = bm, dl = bv;
        const float* xr = xsh + c * NBLK;
        #pragma unroll
        for (int k = 0; k < NBLK; k++) {
            float xv = xr[k];
            dm = fmaf(xv, wm[k], dm);
            dl = fmaf(xv, wl[k], dl);
        }
        float w = wsh[c];
        am = fmaf(w, dm, am);
        ae = fmaf(w, expf(dl) + dm * dm, ae);
    }
    float var = ae - am * am;
    float sg = sqrtf(fmaxf(var, 1e-8f));
    size_t o = (size_t)bl * HID + t;
    out[4096 + o] = am;                              // mu_word
    out[4096 + (size_t)B_IMG * L_W * HID + o] = sg;  // sigma_word
}

// ---------------- launch ----------------
extern "C" void kernel_launch(void* const* d_in, const int* in_sizes, int n_in,
                              void* d_out, int out_size) {
    const float* images   = (const float*)d_in[0];
    const float* captions = (const float*)d_in[1];
    const int*   depends  = (const int*)d_in[2];
    const float* W_gc     = (const float*)d_in[3];
    const float* W_mu     = (const float*)d_in[4];
    const float* b_mu     = (const float*)d_in[5];
    const float* W_lv     = (const float*)d_in[6];
    const float* b_lv     = (const float*)d_in[7];
    const float* W1       = (const float*)d_in[8];
    const float* b1       = (const float*)d_in[9];
    const float* W2       = (const float*)d_in[10];
    const float* b2       = (const float*)d_in[11];
    float* out = (float*)d_out;

    static bool attr_set = false;
    if (!attr_set) {
        cudaFuncSetAttribute(k_caption, cudaFuncAttributeMaxDynamicSharedMemorySize,
                             A_SMEM_FLOATS * sizeof(float));
        attr_set = true;
    }

    float* attn_ptr;
    cudaGetSymbolAddress((void**)&attn_ptr, g_attn);

    // 1) composed 512x32 weight matrices
    k_compose<<<dim3(HID, 3), 32>>>(W_gc, W_mu, W_lv, W1);
    // 2) per-caption graph scalar s[l]
    k_caption<<<C_CAP, 256, A_SMEM_FLOATS * sizeof(float)>>>(captions, depends);
    // 3) logits GEMM (2304 x 2048 x 1024)
    k_gemm_nt<<<dim3(16, 18), 256>>>(images, captions, attn_ptr);
    // 4) fused attention / wctx / tnode / sim per (caption, image)
    k_fused<<<dim3(C_CAP, B_IMG), 512>>>(images, captions, b1, W2, b2, out);
    // 5) softmax over captions
    k_softmax<<<B_IMG, 64>>>(out);
    // 6) weighted Gaussian moments -> mu_word, sigma_word
    k_moments<<<B_IMG * L_W, 512>>>(b_mu, b_lv, out);
}

// round 3
// speedup vs baseline: 1.6233x; 1.3876x over previous
#include <cuda_runtime.h>
#include <math.h>
#include <stdint.h>

// ---------------- dims ----------------
#define B_IMG 64
#define R_REG 36
#define E_DIM 1024
#define C_CAP 64
#define L_W   32
#define N_DEP 30
#define NBLK  32
#define BLK   32
#define HID   512
#define LAM   9.0f

// ---------------- scratch ----------------
__device__ float g_attn[(size_t)B_IMG * R_REG * C_CAP * L_W];
__device__ float g_scap[C_CAP * L_W];
__device__ float g_qns[C_CAP * L_W * NBLK];     // caption block norms sqrt(sum q^2)
__device__ float g_x[(size_t)C_CAP * B_IMG * L_W * NBLK];
__device__ float g_w[B_IMG * C_CAP];
__device__ float g_Wmu[HID * NBLK];             // TRANSPOSED: [k][h]
__device__ float g_Wlv[HID * NBLK];             // TRANSPOSED: [k][h]
__device__ float g_W1c[HID * NBLK];             // TRANSPOSED: [k][h]

// ---------------- compose W @ W_gc, stored transposed [k][h] ----------------
__global__ void k_compose(const float* __restrict__ Wgc,
                          const float* __restrict__ Wmu,
                          const float* __restrict__ Wlv,
                          const float* __restrict__ W1) {
    int h = blockIdx.x;
    int m = blockIdx.y;
    int k = threadIdx.x;  // 0..31
    const float* W = (m == 0) ? Wmu : (m == 1) ? Wlv : W1;
    float acc = 0.f;
    #pragma unroll 8
    for (int j = 0; j < HID; j++)
        acc += W[h * HID + j] * Wgc[j * NBLK + k];
    float* dst = (m == 0) ? g_Wmu : (m == 1) ? g_Wlv : g_W1c;
    dst[k * HID + h] = acc;  // transposed
}

// ---------------- kernel A: per-caption s[l] + block norms ----------------
#define A_SMEM_FLOATS (32 * 1025 + 1024 + 1024)
__global__ void k_caption(const float* __restrict__ caps,
                          const int* __restrict__ deps) {
    int c = blockIdx.x;
    int t = threadIdx.x;  // 256
    extern __shared__ float sh[];
    float* cs  = sh;                  // [32][1025]
    float* G   = cs + 32 * 1025;
    float* adj = G + 1024;

    const float* cp = caps + (size_t)c * L_W * E_DIM;
    for (int i = t; i < L_W * E_DIM; i += 256) {
        int l = i >> 10, e = i & 1023;
        cs[l * 1025 + e] = cp[i];
    }
    __syncthreads();

    // block norms
    for (int p = t; p < 1024; p += 256) {
        int l = p >> 5, k = p & 31;
        float s = 0.f;
        #pragma unroll
        for (int j = 0; j < 32; j++) {
            float v = cs[l * 1025 + k * 32 + j];
            s += v * v;
        }
        g_qns[c * 1024 + p] = sqrtf(s);
    }

    for (int p = t; p < 1024; p += 256) {
        int i = p >> 5, j = p & 31;
        float acc = 0.f;
        #pragma unroll 8
        for (int e = 0; e < E_DIM; e++)
            acc += cs[i * 1025 + e] * cs[j * 1025 + e];
        G[p] = acc;
    }
    __syncthreads();

    if (t < 32) {
        float m = -1e30f;
        for (int j = 0; j < 32; j++) m = fmaxf(m, G[t * 32 + j]);
        float s = 0.f;
        for (int j = 0; j < 32; j++) {
            float e = expf(LAM * (G[t * 32 + j] - m));
            G[t * 32 + j] = e;
            s += e;
        }
        float inv = 1.f / s;
        for (int j = 0; j < 32; j++) G[t * 32 + j] *= inv;
    }
    for (int p = t; p < 1024; p += 256) adj[p] = 0.f;
    __syncthreads();
    if (t == 0) {
        for (int i = 1; i < N_DEP; i++) {
            int a = deps[c * (N_DEP * 2) + i * 2 + 0];
            int b = deps[c * (N_DEP * 2) + i * 2 + 1];
            adj[a * 32 + b] = 1.f;
            adj[b * 32 + a] = 1.f;
        }
        for (int i = 0; i < 32; i++) adj[i * 32 + i] += 1.f;
    }
    __syncthreads();
    if (t < 32) {
        float ss = 0.f;
        for (int j = 0; j < 32; j++) {
            float m2 = adj[t * 32 + j] * G[t * 32 + j];
            ss += m2 * m2;
        }
        float inv = 1.f / (sqrtf(ss) + 1e-8f);
        float s = 0.f;
        for (int j = 0; j < 32; j++) {
            float a = adj[t * 32 + j];
            s += a * G[t * 32 + j] * inv * a;
        }
        g_scap[c * 32 + t] = s;
    }
}

// ---------------- kernel B: logits GEMM (double-buffered) ----------------
__global__ void __launch_bounds__(256) k_gemm_nt(const float* __restrict__ A,
                                                 const float* __restrict__ B,
                                                 float* __restrict__ C) {
    __shared__ float As[2][8][132];
    __shared__ float Bs[2][8][132];
    int tm = blockIdx.y, tn = blockIdx.x;
    int t = threadIdx.x;
    int ty = t >> 4, tx = t & 15;
    int lr = t >> 1;
    int lk = (t & 1) * 4;
    const float* Ab = A + (size_t)(tm * 128 + lr) * E_DIM + lk;
    const float* Bb = B + (size_t)(tn * 128 + lr) * E_DIM + lk;
    float acc[8][8];
    #pragma unroll
    for (int i = 0; i < 8; i++)
        #pragma unroll
        for (int j = 0; j < 8; j++) acc[i][j] = 0.f;

    float4 av = *(const float4*)(Ab);
    float4 bv = *(const float4*)(Bb);
    As[0][lk + 0][lr] = av.x; As[0][lk + 1][lr] = av.y;
    As[0][lk + 2][lr] = av.z; As[0][lk + 3][lr] = av.w;
    Bs[0][lk + 0][lr] = bv.x; Bs[0][lk + 1][lr] = bv.y;
    Bs[0][lk + 2][lr] = bv.z; Bs[0][lk + 3][lr] = bv.w;
    __syncthreads();

    int p = 0;
    for (int k0 = 0; k0 < E_DIM; k0 += 8) {
        if (k0 + 8 < E_DIM) {
            av = *(const float4*)(Ab + k0 + 8);
            bv = *(const float4*)(Bb + k0 + 8);
        }
        #pragma unroll
        for (int k = 0; k < 8; k++) {
            float4 a0 = *(const float4*)&As[p][k][ty * 4];
            float4 a1 = *(const float4*)&As[p][k][64 + ty * 4];
            float4 b0 = *(const float4*)&Bs[p][k][tx * 4];
            float4 b1 = *(const float4*)&Bs[p][k][64 + tx * 4];
            float a_[8] = {a0.x, a0.y, a0.z, a0.w, a1.x, a1.y, a1.z, a1.w};
            float b_[8] = {b0.x, b0.y, b0.z, b0.w, b1.x, b1.y, b1.z, b1.w};
            #pragma unroll
            for (int i = 0; i < 8; i++)
                #pragma unroll
                for (int j = 0; j < 8; j++)
                    acc[i][j] += a_[i] * b_[j];
        }
        if (k0 + 8 < E_DIM) {
            int q = p ^ 1;
            As[q][lk + 0][lr] = av.x; As[q][lk + 1][lr] = av.y;
            As[q][lk + 2][lr] = av.z; As[q][lk + 3][lr] = av.w;
            Bs[q][lk + 0][lr] = bv.x; Bs[q][lk + 1][lr] = bv.y;
            Bs[q][lk + 2][lr] = bv.z; Bs[q][lk + 3][lr] = bv.w;
            __syncthreads();
            p = q;
        }
    }
    const int N = C_CAP * L_W;
    #pragma unroll
    for (int i = 0; i < 8; i++) {
        int row = tm * 128 + ((i < 4) ? (ty * 4 + i) : (64 + ty * 4 + (i - 4)));
        float4 v0 = make_float4(acc[i][0], acc[i][1], acc[i][2], acc[i][3]);
        float4 v1 = make_float4(acc[i][4], acc[i][5], acc[i][6], acc[i][7]);
        *(float4*)(C + (size_t)row * N + tn * 128 + tx * 4) = v0;
        *(float4*)(C + (size_t)row * N + tn * 128 + 64 + tx * 4) = v1;
    }
}

// ---------------- kernel C: fused per-(c,b) ----------------
__global__ void __launch_bounds__(512) k_fused(const float* __restrict__ imgs,
                                               const float* __restrict__ caps,
                                               const float* __restrict__ b1,
                                               const float* __restrict__ W2,
                                               const float* __restrict__ b2,
                                               float* __restrict__ out_sim) {
    int c = blockIdx.x;
    int b = blockIdx.y;
    int t = threadIdx.x;  // 512 = 16 warps
    int warp = t >> 5, lane = t & 31;
    __shared__ float tnorm[L_W * 37];         // [word l][37] padded, word-major
    __shared__ float wlr[L_W * R_REG];        // [l][36], 16B aligned rows
    __shared__ float xs[L_W * NBLK];
    __shared__ float ssc[L_W];
    __shared__ float qsh[L_W * NBLK];
    __shared__ float red[16];

    // stage caption block norms + s[l]
    for (int i = t; i < 1024; i += 512) qsh[i] = g_qns[c * 1024 + i];
    if (t < L_W) ssc[t] = g_scap[c * L_W + t];

    // phase 1 (coalesced): warp handles region r = warp + 16p; lane = word
    #pragma unroll
    for (int p = 0; p < 3; p++) {
        int r = warp + p * 16;
        if (r < R_REG) {
            float a = g_attn[((size_t)(b * R_REG + r)) * (C_CAP * L_W) + c * L_W + lane];
            a = (a >= 0.f) ? a : 0.1f * a;
            float ss = a * a;
            #pragma unroll
            for (int o = 16; o; o >>= 1) ss += __shfl_xor_sync(0xffffffffu, ss, o);
            tnorm[lane * 37 + r] = a * (1.f / (sqrtf(ss) + 1e-8f));
        }
    }
    __syncthreads();
    // softmax over regions per word
    if (t < L_W) {
        float m = -1e30f;
        #pragma unroll
        for (int r = 0; r < R_REG; r++) m = fmaxf(m, tnorm[t * 37 + r]);
        float s = 0.f;
        float e[R_REG];
        #pragma unroll
        for (int r = 0; r < R_REG; r++) {
            e[r] = expf(LAM * (tnorm[t * 37 + r] - m));
            s += e[r];
        }
        float inv = 1.f / s;
        #pragma unroll
        for (int r = 0; r < R_REG; r++) wlr[t * R_REG + r] = e[r] * inv;
    }
    __syncthreads();

    // phase 2+3: warp owns blocks (warp, warp+16); lane = element within block
    int e0 = warp * 32 + lane;
    int e1 = e0 + 512;
    const float* imgb = imgs + (size_t)b * R_REG * E_DIM;
    const float* capc = caps + (size_t)c * L_W * E_DIM;
    float col0[R_REG], col1[R_REG];
    #pragma unroll
    for (int r = 0; r < R_REG; r++) {
        col0[r] = imgb[r * E_DIM + e0];
        col1[r] = imgb[r * E_DIM + e1];
    }
    #pragma unroll 2
    for (int l = 0; l < L_W; l++) {
        const float4* wl4 = (const float4*)(wlr + l * R_REG);
        float w0 = 0.f, w1 = 0.f;
        #pragma unroll
        for (int r4 = 0; r4 < 9; r4++) {
            float4 wv = wl4[r4];
            w0 = fmaf(wv.x, col0[r4 * 4 + 0], w0);
            w1 = fmaf(wv.x, col1[r4 * 4 + 0], w1);
            w0 = fmaf(wv.y, col0[r4 * 4 + 1], w0);
            w1 = fmaf(wv.y, col1[r4 * 4 + 1], w1);
            w0 = fmaf(wv.z, col0[r4 * 4 + 2], w0);
            w1 = fmaf(wv.z, col1[r4 * 4 + 2], w1);
            w0 = fmaf(wv.w, col0[r4 * 4 + 3], w0);
            w1 = fmaf(wv.w, col1[r4 * 4 + 3], w1);
        }
        float q0 = capc[l * E_DIM + e0];
        float q1 = capc[l * E_DIM + e1];
        float n0 = q0 * w0, c0 = w0 * w0;
        float n1 = q1 * w1, c1 = w1 * w1;
        #pragma unroll
        for (int o = 16; o; o >>= 1) {
            n0 += __shfl_xor_sync(0xffffffffu, n0, o);
            c0 += __shfl_xor_sync(0xffffffffu, c0, o);
            n1 += __shfl_xor_sync(0xffffffffu, n1, o);
            c1 += __shfl_xor_sync(0xffffffffu, c1, o);
        }
        if (lane == 0) {
            float sc = ssc[l];
            float d0 = fmaxf(qsh[l * 32 + warp] * sqrtf(c0), 1e-8f);
            float d1 = fmaxf(qsh[l * 32 + warp + 16] * sqrtf(c1), 1e-8f);
            xs[l * NBLK + warp] = (n0 / d0) * sc;
            xs[l * NBLK + warp + 16] = (n1 / d1) * sc;
        }
    }
    __syncthreads();

    // write x to gmem (coalesced float4)
    if (t < 256) {
        float4* xo4 = (float4*)(g_x + (size_t)(c * B_IMG + b) * (L_W * NBLK));
        xo4[t] = ((const float4*)xs)[t];
    }

    // phase 4: sim = mean_l( tanh(x @ W1c^T + b1) @ W2 ) + b2
    float w1r[NBLK];
    #pragma unroll
    for (int k = 0; k < NBLK; k++) w1r[k] = g_W1c[k * HID + t];  // transposed, coalesced
    float bb1 = b1[t];
    float w2 = W2[t];
    float acc = 0.f;
    #pragma unroll 4
    for (int l = 0; l < L_W; l++) {
        const float4* x4 = (const float4*)(xs + l * NBLK);
        float d = bb1;
        #pragma unroll
        for (int k4 = 0; k4 < 8; k4++) {
            float4 xv = x4[k4];
            d = fmaf(xv.x, w1r[k4 * 4 + 0], d);
            d = fmaf(xv.y, w1r[k4 * 4 + 1], d);
            d = fmaf(xv.z, w1r[k4 * 4 + 2], d);
            d = fmaf(xv.w, w1r[k4 * 4 + 3], d);
        }
        acc += tanhf(d) * w2;
    }
    #pragma unroll
    for (int o = 16; o; o >>= 1) acc += __shfl_down_sync(0xffffffffu, acc, o);
    if (lane == 0) red[warp] = acc;
    __syncthreads();
    if (t == 0) {
        float s = 0.f;
        #pragma unroll
        for (int i = 0; i < 16; i++) s += red[i];
        out_sim[b * C_CAP + c] = s * (1.f / 32.f) + b2[0];
    }
}

// ---------------- kernel D: softmax over captions ----------------
__global__ void k_softmax(const float* __restrict__ sims) {
    int b = blockIdx.x;
    int t = threadIdx.x;  // 64
    __shared__ float sh[64];
    __shared__ float mx, sm;
    float v = sims[b * C_CAP + t];
    sh[t] = v;
    __syncthreads();
    if (t == 0) {
        float m = sh[0];
        for (int i = 1; i < 64; i++) m = fmaxf(m, sh[i]);
        mx = m;
    }
    __syncthreads();
    float e = expf(v - mx);
    sh[t] = e;
    __syncthreads();
    if (t == 0) {
        float s = 0.f;
        for (int i = 0; i < 64; i++) s += sh[i];
        sm = s;
    }
    __syncthreads();
    g_w[b * C_CAP + t] = e / sm;
}

// ---------------- kernel E: weighted Gaussian moments ----------------
__global__ void __launch_bounds__(512) k_moments(const float* __restrict__ bmu,
                                                 const float* __restrict__ blv,
                                                 float* __restrict__ out) {
    int bl = blockIdx.x;        // b*32 + l
    int b = bl >> 5, l = bl & 31;
    int t = threadIdx.x;        // 512 (h)
    __shared__ float xsh[C_CAP * NBLK];  // [c][k]
    __shared__ float wsh[C_CAP];
    for (int i = t; i < C_CAP * NBLK / 4; i += 512) {
        int c = i >> 3, k4 = i & 7;
        ((float4*)xsh)[i] = *(const float4*)(g_x + (size_t)(c * B_IMG + b) * (L_W * NBLK) + l * NBLK + k4 * 4);
    }
    if (t < C_CAP) wsh[t] = g_w[b * C_CAP + t];
    __syncthreads();

    float wm[NBLK], wl[NBLK];
    #pragma unroll
    for (int k = 0; k < NBLK; k++) {
        wm[k] = g_Wmu[k * HID + t];  // transposed, coalesced
        wl[k] = g_Wlv[k * HID + t];
    }
    float bm = bmu[t], bv = blv[t];
    float am = 0.f, ae = 0.f;
    #pragma unroll 2
    for (int c = 0; c < C_CAP; c++) {
        const float4* xr4 = (const float4*)(xsh + c * NBLK);
        float dm = bm, dl = bv;
        #pragma unroll
        for (int k4 = 0; k4 < 8; k4++) {
            float4 xv = xr4[k4];
            dm = fmaf(xv.x, wm[k4 * 4 + 0], dm);
            dl = fmaf(xv.x, wl[k4 * 4 + 0], dl);
            dm = fmaf(xv.y, wm[k4 * 4 + 1], dm);
            dl = fmaf(xv.y, wl[k4 * 4 + 1], dl);
            dm = fmaf(xv.z, wm[k4 * 4 + 2], dm);
            dl = fmaf(xv.z, wl[k4 * 4 + 2], dl);
            dm = fmaf(xv.w, wm[k4 * 4 + 3], dm);
            dl = fmaf(xv.w, wl[k4 * 4 + 3], dl);
        }
        float w = wsh[c];
        am = fmaf(w, dm, am);
        ae = fmaf(w, expf(dl) + dm * dm, ae);
    }
    float var = ae - am * am;
    float sg = sqrtf(fmaxf(var, 1e-8f));
    size_t o = (size_t)bl * HID + t;
    out[4096 + o] = am;
    out[4096 + (size_t)B_IMG * L_W * HID + o] = sg;
}

// ---------------- launch ----------------
extern "C" void kernel_launch(void* const* d_in, const int* in_sizes, int n_in,
                              void* d_out, int out_size) {
    const float* images   = (const float*)d_in[0];
    const float* captions = (const float*)d_in[1];
    const int*   depends  = (const int*)d_in[2];
    const float* W_gc     = (const float*)d_in[3];
    const float* W_mu     = (const float*)d_in[4];
    const float* b_mu     = (const float*)d_in[5];
    const float* W_lv     = (const float*)d_in[6];
    const float* b_lv     = (const float*)d_in[7];
    const float* W1       = (const float*)d_in[8];
    const float* b1       = (const float*)d_in[9];
    const float* W2       = (const float*)d_in[10];
    const float* b2       = (const float*)d_in[11];
    float* out = (float*)d_out;

    static bool attr_set = false;
    if (!attr_set) {
        cudaFuncSetAttribute(k_caption, cudaFuncAttributeMaxDynamicSharedMemorySize,
                             A_SMEM_FLOATS * sizeof(float));
        attr_set = true;
    }

    float* attn_ptr;
    cudaGetSymbolAddress((void**)&attn_ptr, g_attn);

    k_compose<<<dim3(HID, 3), 32>>>(W_gc, W_mu, W_lv, W1);
    k_caption<<<C_CAP, 256, A_SMEM_FLOATS * sizeof(float)>>>(captions, depends);
    k_gemm_nt<<<dim3(16, 18), 256>>>(images, captions, attn_ptr);
    k_fused<<<dim3(C_CAP, B_IMG), 512>>>(images, captions, b1, W2, b2, out);
    k_softmax<<<B_IMG, 64>>>(out);
    k_moments<<<B_IMG * L_W, 512>>>(b_mu, b_lv, out);
}

// round 4
// speedup vs baseline: 1.7892x; 1.1022x over previous
#include <cuda_runtime.h>
#include <math.h>
#include <stdint.h>

// ---------------- dims ----------------
#define B_IMG 64
#define R_REG 36
#define E_DIM 1024
#define C_CAP 64
#define L_W   32
#define N_DEP 30
#define NBLK  32
#define BLK   32
#define HID   512
#define LAM   9.0f

typedef unsigned long long ull;

// f32x2 packed helpers (sm_100+ PTX)
#define PK2(d, lo, hi)   asm("mov.b64 %0, {%1, %2};" : "=l"(d) : "f"(lo), "f"(hi))
#define UPK2(lo, hi, s)  asm("mov.b64 {%0, %1}, %2;" : "=f"(lo), "=f"(hi) : "l"(s))
#define FFMA2(d, a, b, c) asm("fma.rn.f32x2 %0, %1, %2, %3;" : "=l"(d) : "l"(a), "l"(b), "l"(c))
#define FADD2(d, a, b)    asm("add.rn.f32x2 %0, %1, %2;" : "=l"(d) : "l"(a), "l"(b))

// ---------------- scratch ----------------
__device__ float g_attn[(size_t)B_IMG * R_REG * C_CAP * L_W];
__device__ float g_scap[C_CAP * L_W];
__device__ float g_qns[C_CAP * L_W * NBLK];
__device__ float g_x[(size_t)C_CAP * B_IMG * L_W * NBLK];
__device__ float g_w[B_IMG * C_CAP];
__device__ float2 g_Wml[NBLK * HID];            // [k][h] -> (wmu, wlv) interleaved
__device__ float g_W1c[NBLK * HID];             // transposed [k][h]

// ---------------- compose W @ W_gc ----------------
__global__ void k_compose(const float* __restrict__ Wgc,
                          const float* __restrict__ Wmu,
                          const float* __restrict__ Wlv,
                          const float* __restrict__ W1) {
    int h = blockIdx.x;
    int m = blockIdx.y;
    int k = threadIdx.x;  // 0..31
    const float* W = (m == 0) ? Wmu : (m == 1) ? Wlv : W1;
    float acc = 0.f;
    #pragma unroll 8
    for (int j = 0; j < HID; j++)
        acc += W[h * HID + j] * Wgc[j * NBLK + k];
    if (m == 0)      g_Wml[k * HID + h].x = acc;
    else if (m == 1) g_Wml[k * HID + h].y = acc;
    else             g_W1c[k * HID + h] = acc;
}

// ---------------- kernel A: per-caption s[l] + block norms ----------------
#define A_SMEM_FLOATS (32 * 1025 + 1024 + 1024)
__global__ void k_caption(const float* __restrict__ caps,
                          const int* __restrict__ deps) {
    int c = blockIdx.x;
    int t = threadIdx.x;  // 256
    extern __shared__ float sh[];
    float* cs  = sh;                  // [32][1025]
    float* G   = cs + 32 * 1025;
    float* adj = G + 1024;

    const float* cp = caps + (size_t)c * L_W * E_DIM;
    for (int i = t; i < L_W * E_DIM; i += 256) {
        int l = i >> 10, e = i & 1023;
        cs[l * 1025 + e] = cp[i];
    }
    __syncthreads();

    for (int p = t; p < 1024; p += 256) {
        int l = p >> 5, k = p & 31;
        float s = 0.f;
        #pragma unroll
        for (int j = 0; j < 32; j++) {
            float v = cs[l * 1025 + k * 32 + j];
            s += v * v;
        }
        g_qns[c * 1024 + p] = sqrtf(s);
    }

    for (int p = t; p < 1024; p += 256) {
        int i = p >> 5, j = p & 31;
        float acc = 0.f;
        #pragma unroll 8
        for (int e = 0; e < E_DIM; e++)
            acc += cs[i * 1025 + e] * cs[j * 1025 + e];
        G[p] = acc;
    }
    __syncthreads();

    if (t < 32) {
        float m = -1e30f;
        for (int j = 0; j < 32; j++) m = fmaxf(m, G[t * 32 + j]);
        float s = 0.f;
        for (int j = 0; j < 32; j++) {
            float e = expf(LAM * (G[t * 32 + j] - m));
            G[t * 32 + j] = e;
            s += e;
        }
        float inv = 1.f / s;
        for (int j = 0; j < 32; j++) G[t * 32 + j] *= inv;
    }
    for (int p = t; p < 1024; p += 256) adj[p] = 0.f;
    __syncthreads();
    if (t == 0) {
        for (int i = 1; i < N_DEP; i++) {
            int a = deps[c * (N_DEP * 2) + i * 2 + 0];
            int b = deps[c * (N_DEP * 2) + i * 2 + 1];
            adj[a * 32 + b] = 1.f;
            adj[b * 32 + a] = 1.f;
        }
        for (int i = 0; i < 32; i++) adj[i * 32 + i] += 1.f;
    }
    __syncthreads();
    if (t < 32) {
        float ss = 0.f;
        for (int j = 0; j < 32; j++) {
            float m2 = adj[t * 32 + j] * G[t * 32 + j];
            ss += m2 * m2;
        }
        float inv = 1.f / (sqrtf(ss) + 1e-8f);
        float s = 0.f;
        for (int j = 0; j < 32; j++) {
            float a = adj[t * 32 + j];
            s += a * G[t * 32 + j] * inv * a;
        }
        g_scap[c * 32 + t] = s;
    }
}

// ---------------- kernel B: logits GEMM, f32x2 packed ----------------
__global__ void __launch_bounds__(256) k_gemm_nt(const float* __restrict__ A,
                                                 const float* __restrict__ B,
                                                 float* __restrict__ C) {
    __shared__ __align__(16) float As[2][8][132];
    __shared__ __align__(16) float Bs[2][8][132];
    int tm = blockIdx.y, tn = blockIdx.x;
    int t = threadIdx.x;
    int ty = t >> 4, tx = t & 15;
    int lr = t >> 1;
    int lk = (t & 1) * 4;
    const float* Ab = A + (size_t)(tm * 128 + lr) * E_DIM + lk;
    const float* Bb = B + (size_t)(tn * 128 + lr) * E_DIM + lk;
    ull acc[8][4];
    #pragma unroll
    for (int i = 0; i < 8; i++)
        #pragma unroll
        for (int j = 0; j < 4; j++) acc[i][j] = 0ULL;

    float4 av = *(const float4*)(Ab);
    float4 bv = *(const float4*)(Bb);
    As[0][lk + 0][lr] = av.x; As[0][lk + 1][lr] = av.y;
    As[0][lk + 2][lr] = av.z; As[0][lk + 3][lr] = av.w;
    Bs[0][lk + 0][lr] = bv.x; Bs[0][lk + 1][lr] = bv.y;
    Bs[0][lk + 2][lr] = bv.z; Bs[0][lk + 3][lr] = bv.w;
    __syncthreads();

    int p = 0;
    for (int k0 = 0; k0 < E_DIM; k0 += 8) {
        if (k0 + 8 < E_DIM) {
            av = *(const float4*)(Ab + k0 + 8);
            bv = *(const float4*)(Bb + k0 + 8);
        }
        #pragma unroll
        for (int k = 0; k < 8; k++) {
            float4 a0 = *(const float4*)&As[p][k][ty * 4];
            float4 a1 = *(const float4*)&As[p][k][64 + ty * 4];
            ulonglong2 bq0 = *(const ulonglong2*)&Bs[p][k][tx * 4];
            ulonglong2 bq1 = *(const ulonglong2*)&Bs[p][k][64 + tx * 4];
            float a_[8] = {a0.x, a0.y, a0.z, a0.w, a1.x, a1.y, a1.z, a1.w};
            #pragma unroll
            for (int i = 0; i < 8; i++) {
                ull ai2; PK2(ai2, a_[i], a_[i]);
                FFMA2(acc[i][0], ai2, bq0.x, acc[i][0]);
                FFMA2(acc[i][1], ai2, bq0.y, acc[i][1]);
                FFMA2(acc[i][2], ai2, bq1.x, acc[i][2]);
                FFMA2(acc[i][3], ai2, bq1.y, acc[i][3]);
            }
        }
        if (k0 + 8 < E_DIM) {
            int q = p ^ 1;
            As[q][lk + 0][lr] = av.x; As[q][lk + 1][lr] = av.y;
            As[q][lk + 2][lr] = av.z; As[q][lk + 3][lr] = av.w;
            Bs[q][lk + 0][lr] = bv.x; Bs[q][lk + 1][lr] = bv.y;
            Bs[q][lk + 2][lr] = bv.z; Bs[q][lk + 3][lr] = bv.w;
            __syncthreads();
            p = q;
        }
    }
    const int N = C_CAP * L_W;
    #pragma unroll
    for (int i = 0; i < 8; i++) {
        int row = tm * 128 + ((i < 4) ? (ty * 4 + i) : (64 + ty * 4 + (i - 4)));
        float c0, c1, c2, c3, c4, c5, c6, c7;
        UPK2(c0, c1, acc[i][0]); UPK2(c2, c3, acc[i][1]);
        UPK2(c4, c5, acc[i][2]); UPK2(c6, c7, acc[i][3]);
        *(float4*)(C + (size_t)row * N + tn * 128 + tx * 4) = make_float4(c0, c1, c2, c3);
        *(float4*)(C + (size_t)row * N + tn * 128 + 64 + tx * 4) = make_float4(c4, c5, c6, c7);
    }
}

// ---------------- kernel C: fused per-(c,b), f32x2 + folded reductions ----------------
__global__ void __launch_bounds__(512) k_fused(const float* __restrict__ imgs,
                                               const float* __restrict__ caps,
                                               const float* __restrict__ b1,
                                               const float* __restrict__ W2,
                                               const float* __restrict__ b2,
                                               float* __restrict__ out_sim) {
    int c = blockIdx.x;
    int b = blockIdx.y;
    int t = threadIdx.x;  // 512 = 16 warps
    int warp = t >> 5, lane = t & 31;
    __shared__ __align__(16) float tnorm[L_W * 37];
    __shared__ __align__(16) float wlr2[L_W * 72];   // duplicated pairs (w,w) per r
    __shared__ __align__(16) float xs[L_W * NBLK];   // [l][k]
    __shared__ float ssc[L_W];
    __shared__ __align__(16) float qsh[L_W * NBLK];
    __shared__ float red[16];

    for (int i = t; i < 1024; i += 512) qsh[i] = g_qns[c * 1024 + i];
    if (t < L_W) ssc[t] = g_scap[c * L_W + t];

    // phase 1 (coalesced): warp = region, lane = word
    #pragma unroll
    for (int p = 0; p < 3; p++) {
        int r = warp + p * 16;
        if (r < R_REG) {
            float a = g_attn[((size_t)(b * R_REG + r)) * (C_CAP * L_W) + c * L_W + lane];
            a = (a >= 0.f) ? a : 0.1f * a;
            float ss = a * a;
            #pragma unroll
            for (int o = 16; o; o >>= 1) ss += __shfl_xor_sync(0xffffffffu, ss, o);
            tnorm[lane * 37 + r] = a * (1.f / (sqrtf(ss) + 1e-8f));
        }
    }
    __syncthreads();
    // softmax over regions per word; write duplicated (w,w) pairs
    if (t < L_W) {
        float m = -1e30f;
        #pragma unroll
        for (int r = 0; r < R_REG; r++) m = fmaxf(m, tnorm[t * 37 + r]);
        float s = 0.f;
        float e[R_REG];
        #pragma unroll
        for (int r = 0; r < R_REG; r++) {
            e[r] = expf(LAM * (tnorm[t * 37 + r] - m));
            s += e[r];
        }
        float inv = 1.f / s;
        #pragma unroll
        for (int r = 0; r < R_REG; r++) {
            float w = e[r] * inv;
            ((float2*)(wlr2 + t * 72))[r] = make_float2(w, w);
        }
    }
    __syncthreads();

    // phase 2+3: warp owns blocks (warp, warp+16); lane = element in block
    int e0 = warp * 32 + lane;
    int e1 = e0 + 512;
    const float* imgb = imgs + (size_t)b * R_REG * E_DIM;
    const float* capc = caps + (size_t)c * L_W * E_DIM;
    ull col2[R_REG];
    #pragma unroll
    for (int r = 0; r < R_REG; r++) {
        float v0 = imgb[r * E_DIM + e0];
        float v1 = imgb[r * E_DIM + e1];
        PK2(col2[r], v0, v1);
    }
    #pragma unroll 2
    for (int l = 0; l < L_W; l++) {
        const ulonglong2* wl4 = (const ulonglong2*)(wlr2 + l * 72);
        ull accA = 0ULL, accB = 0ULL;
        #pragma unroll
        for (int r2 = 0; r2 < 18; r2++) {
            ulonglong2 wq = wl4[r2];
            FFMA2(accA, wq.x, col2[r2 * 2 + 0], accA);
            FFMA2(accB, wq.y, col2[r2 * 2 + 1], accB);
        }
        ull wsum; FADD2(wsum, accA, accB);
        float w0, w1; UPK2(w0, w1, wsum);
        float q0 = capc[l * E_DIM + e0];
        float q1 = capc[l * E_DIM + e1];
        float n0 = q0 * w0, c0 = w0 * w0;
        float n1 = q1 * w1, c1 = w1 * w1;
        // folded reduction: 4 values -> 7 shfl
        bool hi16 = (lane & 16) != 0;
        float van = hi16 ? n1 : n0, oan = hi16 ? n0 : n1;
        float rn = van + __shfl_xor_sync(0xffffffffu, oan, 16);
        float vac = hi16 ? c1 : c0, oac = hi16 ? c0 : c1;
        float rc = vac + __shfl_xor_sync(0xffffffffu, oac, 16);
        bool hi8 = (lane & 8) != 0;
        float vb = hi8 ? rc : rn, ob = hi8 ? rn : rc;
        float r = vb + __shfl_xor_sync(0xffffffffu, ob, 8);
        r += __shfl_xor_sync(0xffffffffu, r, 4);
        r += __shfl_xor_sync(0xffffffffu, r, 2);
        r += __shfl_xor_sync(0xffffffffu, r, 1);
        // lane0=n0, lane8=c0, lane16=n1, lane24=c1
        float cpart = __shfl_sync(0xffffffffu, r, (lane & 16) | 8);
        if ((lane & 15) == 0) {
            int kblk = warp + (lane & 16);
            float den = fmaxf(qsh[l * 32 + kblk] * sqrtf(cpart), 1e-8f);
            xs[l * NBLK + kblk] = (r / den) * ssc[l];
        }
    }
    __syncthreads();

    // write x to gmem
    if (t < 256) {
        float4* xo4 = (float4*)(g_x + (size_t)(c * B_IMG + b) * (L_W * NBLK));
        xo4[t] = ((const float4*)xs)[t];
    }

    // phase 4: sim = mean_l( tanh(x @ W1c^T + b1) @ W2 ) + b2  (f32x2 along k)
    ull w1p[16];
    {
        float wr[NBLK];
        #pragma unroll
        for (int k = 0; k < NBLK; k++) wr[k] = g_W1c[k * HID + t];
        #pragma unroll
        for (int j = 0; j < 16; j++) PK2(w1p[j], wr[2 * j], wr[2 * j + 1]);
    }
    float bb1 = b1[t];
    float w2 = W2[t];
    float acc = 0.f;
    #pragma unroll 4
    for (int l = 0; l < L_W; l++) {
        const ulonglong2* x4 = (const ulonglong2*)(xs + l * NBLK);
        ull d2; PK2(d2, bb1, 0.f);
        #pragma unroll
        for (int j = 0; j < 8; j++) {
            ulonglong2 xq = x4[j];
            FFMA2(d2, xq.x, w1p[2 * j + 0], d2);
            FFMA2(d2, xq.y, w1p[2 * j + 1], d2);
        }
        float dlo, dhi; UPK2(dlo, dhi, d2);
        acc += tanhf(dlo + dhi) * w2;
    }
    #pragma unroll
    for (int o = 16; o; o >>= 1) acc += __shfl_down_sync(0xffffffffu, acc, o);
    if (lane == 0) red[warp] = acc;
    __syncthreads();
    if (t == 0) {
        float s = 0.f;
        #pragma unroll
        for (int i = 0; i < 16; i++) s += red[i];
        out_sim[b * C_CAP + c] = s * (1.f / 32.f) + b2[0];
    }
}

// ---------------- kernel D: softmax over captions ----------------
__global__ void k_softmax(const float* __restrict__ sims) {
    int b = blockIdx.x;
    int t = threadIdx.x;  // 64
    __shared__ float sh[64];
    __shared__ float mx, sm;
    float v = sims[b * C_CAP + t];
    sh[t] = v;
    __syncthreads();
    if (t == 0) {
        float m = sh[0];
        for (int i = 1; i < 64; i++) m = fmaxf(m, sh[i]);
        mx = m;
    }
    __syncthreads();
    float e = expf(v - mx);
    sh[t] = e;
    __syncthreads();
    if (t == 0) {
        float s = 0.f;
        for (int i = 0; i < 64; i++) s += sh[i];
        sm = s;
    }
    __syncthreads();
    g_w[b * C_CAP + t] = e / sm;
}

// ---------------- kernel E: weighted Gaussian moments, (dm,dl) packed ----------------
__global__ void __launch_bounds__(512) k_moments(const float* __restrict__ bmu,
                                                 const float* __restrict__ blv,
                                                 float* __restrict__ out) {
    int bl = blockIdx.x;        // b*32 + l
    int b = bl >> 5, l = bl & 31;
    int t = threadIdx.x;        // 512 (h)
    __shared__ __align__(16) float xsh[C_CAP * NBLK];
    __shared__ float wsh[C_CAP];
    for (int i = t; i < C_CAP * NBLK / 4; i += 512) {
        int c = i >> 3, k4 = i & 7;
        ((float4*)xsh)[i] = *(const float4*)(g_x + (size_t)(c * B_IMG + b) * (L_W * NBLK) + l * NBLK + k4 * 4);
    }
    if (t < C_CAP) wsh[t] = g_w[b * C_CAP + t];
    __syncthreads();

    ull wml[NBLK];
    #pragma unroll
    for (int k = 0; k < NBLK; k++)
        wml[k] = *(const ull*)&g_Wml[k * HID + t];   // (wmu, wlv)
    ull bias2; PK2(bias2, bmu[t], blv[t]);
    float am = 0.f, ae = 0.f;
    #pragma unroll 2
    for (int c = 0; c < C_CAP; c++) {
        const float4* xr4 = (const float4*)(xsh + c * NBLK);
        ull d2 = bias2;
        #pragma unroll
        for (int k4 = 0; k4 < 8; k4++) {
            float4 xv = xr4[k4];
            ull x0, x1, x2, x3;
            PK2(x0, xv.x, xv.x); PK2(x1, xv.y, xv.y);
            PK2(x2, xv.z, xv.z); PK2(x3, xv.w, xv.w);
            FFMA2(d2, x0, wml[k4 * 4 + 0], d2);
            FFMA2(d2, x1, wml[k4 * 4 + 1], d2);
            FFMA2(d2, x2, wml[k4 * 4 + 2], d2);
            FFMA2(d2, x3, wml[k4 * 4 + 3], d2);
        }
        float dm, dl; UPK2(dm, dl, d2);
        float w = wsh[c];
        am = fmaf(w, dm, am);
        ae = fmaf(w, expf(dl) + dm * dm, ae);
    }
    float var = ae - am * am;
    float sg = sqrtf(fmaxf(var, 1e-8f));
    size_t o = (size_t)bl * HID + t;
    out[4096 + o] = am;
    out[4096 + (size_t)B_IMG * L_W * HID + o] = sg;
}

// ---------------- launch ----------------
extern "C" void kernel_launch(void* const* d_in, const int* in_sizes, int n_in,
                              void* d_out, int out_size) {
    const float* images   = (const float*)d_in[0];
    const float* captions = (const float*)d_in[1];
    const int*   depends  = (const int*)d_in[2];
    const float* W_gc     = (const float*)d_in[3];
    const float* W_mu     = (const float*)d_in[4];
    const float* b_mu     = (const float*)d_in[5];
    const float* W_lv     = (const float*)d_in[6];
    const float* b_lv     = (const float*)d_in[7];
    const float* W1       = (const float*)d_in[8];
    const float* b1       = (const float*)d_in[9];
    const float* W2       = (const float*)d_in[10];
    const float* b2       = (const float*)d_in[11];
    float* out = (float*)d_out;

    static bool attr_set = false;
    if (!attr_set) {
        cudaFuncSetAttribute(k_caption, cudaFuncAttributeMaxDynamicSharedMemorySize,
                             A_SMEM_FLOATS * sizeof(float));
        attr_set = true;
    }

    float* attn_ptr;
    cudaGetSymbolAddress((void**)&attn_ptr, g_attn);

    k_compose<<<dim3(HID, 3), 32>>>(W_gc, W_mu, W_lv, W1);
    k_caption<<<C_CAP, 256, A_SMEM_FLOATS * sizeof(float)>>>(captions, depends);
    k_gemm_nt<<<dim3(16, 18), 256>>>(images, captions, attn_ptr);
    k_fused<<<dim3(C_CAP, B_IMG), 512>>>(images, captions, b1, W2, b2, out);
    k_softmax<<<B_IMG, 64>>>(out);
    k_moments<<<B_IMG * L_W, 512>>>(b_mu, b_lv, out);
}

// round 5
// speedup vs baseline: 1.9703x; 1.1012x over previous
#include <cuda_runtime.h>
#include <math.h>
#include <stdint.h>

// ---------------- dims ----------------
#define B_IMG 64
#define R_REG 36
#define E_DIM 1024
#define C_CAP 64
#define L_W   32
#define N_DEP 30
#define NBLK  32
#define BLK   32
#define HID   512
#define LAM   9.0f

typedef unsigned long long ull;

// f32x2 packed helpers (sm_100+ PTX)
#define PK2(d, lo, hi)   asm("mov.b64 %0, {%1, %2};" : "=l"(d) : "f"(lo), "f"(hi))
#define UPK2(lo, hi, s)  asm("mov.b64 {%0, %1}, %2;" : "=f"(lo), "=f"(hi) : "l"(s))
#define FFMA2(d, a, b, c) asm("fma.rn.f32x2 %0, %1, %2, %3;" : "=l"(d) : "l"(a), "l"(b), "l"(c))
#define FADD2(d, a, b)    asm("add.rn.f32x2 %0, %1, %2;" : "=l"(d) : "l"(a), "l"(b))
#define TANH_APX(d, a)    asm("tanh.approx.f32 %0, %1;" : "=f"(d) : "f"(a))

// ---------------- scratch ----------------
__device__ float g_attn[(size_t)B_IMG * R_REG * C_CAP * L_W];
__device__ float g_scap[C_CAP * L_W];
__device__ float g_qns[C_CAP * L_W * NBLK];
__device__ float g_x[(size_t)C_CAP * B_IMG * L_W * NBLK];
__device__ float g_w[B_IMG * C_CAP];
__device__ float2 g_Wml[NBLK * HID];            // [k][h] -> (wmu, wlv)
__device__ float g_W1c[NBLK * HID];             // transposed [k][h]

// ---------------- compose W @ W_gc ----------------
__global__ void k_compose(const float* __restrict__ Wgc,
                          const float* __restrict__ Wmu,
                          const float* __restrict__ Wlv,
                          const float* __restrict__ W1) {
    int h = blockIdx.x;
    int m = blockIdx.y;
    int k = threadIdx.x;  // 0..31
    const float* W = (m == 0) ? Wmu : (m == 1) ? Wlv : W1;
    float acc = 0.f;
    #pragma unroll 8
    for (int j = 0; j < HID; j++)
        acc += W[h * HID + j] * Wgc[j * NBLK + k];
    if (m == 0)      g_Wml[k * HID + h].x = acc;
    else if (m == 1) g_Wml[k * HID + h].y = acc;
    else             g_W1c[k * HID + h] = acc;
}

// ---------------- kernel A: per-caption s[l] + block norms ----------------
#define A_SMEM_FLOATS (32 * 1025 + 1024 + 1024)
__global__ void k_caption(const float* __restrict__ caps,
                          const int* __restrict__ deps) {
    int c = blockIdx.x;
    int t = threadIdx.x;  // 256
    extern __shared__ float sh[];
    float* cs  = sh;                  // [32][1025]
    float* G   = cs + 32 * 1025;
    float* adj = G + 1024;

    const float* cp = caps + (size_t)c * L_W * E_DIM;
    for (int i = t; i < L_W * E_DIM; i += 256) {
        int l = i >> 10, e = i & 1023;
        cs[l * 1025 + e] = cp[i];
    }
    __syncthreads();

    for (int p = t; p < 1024; p += 256) {
        int l = p >> 5, k = p & 31;
        float s = 0.f;
        #pragma unroll
        for (int j = 0; j < 32; j++) {
            float v = cs[l * 1025 + k * 32 + j];
            s += v * v;
        }
        g_qns[c * 1024 + p] = sqrtf(s);
    }

    for (int p = t; p < 1024; p += 256) {
        int i = p >> 5, j = p & 31;
        float acc = 0.f;
        #pragma unroll 8
        for (int e = 0; e < E_DIM; e++)
            acc += cs[i * 1025 + e] * cs[j * 1025 + e];
        G[p] = acc;
    }
    __syncthreads();

    if (t < 32) {
        float m = -1e30f;
        for (int j = 0; j < 32; j++) m = fmaxf(m, G[t * 32 + j]);
        float s = 0.f;
        for (int j = 0; j < 32; j++) {
            float e = expf(LAM * (G[t * 32 + j] - m));
            G[t * 32 + j] = e;
            s += e;
        }
        float inv = 1.f / s;
        for (int j = 0; j < 32; j++) G[t * 32 + j] *= inv;
    }
    for (int p = t; p < 1024; p += 256) adj[p] = 0.f;
    __syncthreads();
    if (t == 0) {
        for (int i = 1; i < N_DEP; i++) {
            int a = deps[c * (N_DEP * 2) + i * 2 + 0];
            int b = deps[c * (N_DEP * 2) + i * 2 + 1];
            adj[a * 32 + b] = 1.f;
            adj[b * 32 + a] = 1.f;
        }
        for (int i = 0; i < 32; i++) adj[i * 32 + i] += 1.f;
    }
    __syncthreads();
    if (t < 32) {
        float ss = 0.f;
        for (int j = 0; j < 32; j++) {
            float m2 = adj[t * 32 + j] * G[t * 32 + j];
            ss += m2 * m2;
        }
        float inv = 1.f / (sqrtf(ss) + 1e-8f);
        float s = 0.f;
        for (int j = 0; j < 32; j++) {
            float a = adj[t * 32 + j];
            s += a * G[t * 32 + j] * inv * a;
        }
        g_scap[c * 32 + t] = s;
    }
}

// ---------------- kernel B: logits GEMM, f32x2 packed ----------------
__global__ void __launch_bounds__(256) k_gemm_nt(const float* __restrict__ A,
                                                 const float* __restrict__ B,
                                                 float* __restrict__ C) {
    __shared__ __align__(16) float As[2][8][132];
    __shared__ __align__(16) float Bs[2][8][132];
    int tm = blockIdx.y, tn = blockIdx.x;
    int t = threadIdx.x;
    int ty = t >> 4, tx = t & 15;
    int lr = t >> 1;
    int lk = (t & 1) * 4;
    const float* Ab = A + (size_t)(tm * 128 + lr) * E_DIM + lk;
    const float* Bb = B + (size_t)(tn * 128 + lr) * E_DIM + lk;
    ull acc[8][4];
    #pragma unroll
    for (int i = 0; i < 8; i++)
        #pragma unroll
        for (int j = 0; j < 4; j++) acc[i][j] = 0ULL;

    float4 av = *(const float4*)(Ab);
    float4 bv = *(const float4*)(Bb);
    As[0][lk + 0][lr] = av.x; As[0][lk + 1][lr] = av.y;
    As[0][lk + 2][lr] = av.z; As[0][lk + 3][lr] = av.w;
    Bs[0][lk + 0][lr] = bv.x; Bs[0][lk + 1][lr] = bv.y;
    Bs[0][lk + 2][lr] = bv.z; Bs[0][lk + 3][lr] = bv.w;
    __syncthreads();

    int p = 0;
    for (int k0 = 0; k0 < E_DIM; k0 += 8) {
        if (k0 + 8 < E_DIM) {
            av = *(const float4*)(Ab + k0 + 8);
            bv = *(const float4*)(Bb + k0 + 8);
        }
        #pragma unroll
        for (int k = 0; k < 8; k++) {
            float4 a0 = *(const float4*)&As[p][k][ty * 4];
            float4 a1 = *(const float4*)&As[p][k][64 + ty * 4];
            ulonglong2 bq0 = *(const ulonglong2*)&Bs[p][k][tx * 4];
            ulonglong2 bq1 = *(const ulonglong2*)&Bs[p][k][64 + tx * 4];
            float a_[8] = {a0.x, a0.y, a0.z, a0.w, a1.x, a1.y, a1.z, a1.w};
            #pragma unroll
            for (int i = 0; i < 8; i++) {
                ull ai2; PK2(ai2, a_[i], a_[i]);
                FFMA2(acc[i][0], ai2, bq0.x, acc[i][0]);
                FFMA2(acc[i][1], ai2, bq0.y, acc[i][1]);
                FFMA2(acc[i][2], ai2, bq1.x, acc[i][2]);
                FFMA2(acc[i][3], ai2, bq1.y, acc[i][3]);
            }
        }
        if (k0 + 8 < E_DIM) {
            int q = p ^ 1;
            As[q][lk + 0][lr] = av.x; As[q][lk + 1][lr] = av.y;
            As[q][lk + 2][lr] = av.z; As[q][lk + 3][lr] = av.w;
            Bs[q][lk + 0][lr] = bv.x; Bs[q][lk + 1][lr] = bv.y;
            Bs[q][lk + 2][lr] = bv.z; Bs[q][lk + 3][lr] = bv.w;
            __syncthreads();
            p = q;
        }
    }
    const int N = C_CAP * L_W;
    #pragma unroll
    for (int i = 0; i < 8; i++) {
        int row = tm * 128 + ((i < 4) ? (ty * 4 + i) : (64 + ty * 4 + (i - 4)));
        float c0, c1, c2, c3, c4, c5, c6, c7;
        UPK2(c0, c1, acc[i][0]); UPK2(c2, c3, acc[i][1]);
        UPK2(c4, c5, acc[i][2]); UPK2(c6, c7, acc[i][3]);
        *(float4*)(C + (size_t)row * N + tn * 128 + tx * 4) = make_float4(c0, c1, c2, c3);
        *(float4*)(C + (size_t)row * N + tn * 128 + 64 + tx * 4) = make_float4(c4, c5, c6, c7);
    }
}

// ---------------- kernel C: fused per-(c,b), natural-pair f32x2 ----------------
__global__ void __launch_bounds__(512) k_fused(const float* __restrict__ imgs,
                                               const float* __restrict__ caps,
                                               const float* __restrict__ b1,
                                               const float* __restrict__ W2,
                                               const float* __restrict__ b2,
                                               float* __restrict__ out_sim) {
    int c = blockIdx.x;
    int b = blockIdx.y;
    int t = threadIdx.x;  // 512 = 16 warps
    int warp = t >> 5, lane = t & 31;
    __shared__ __align__(16) float tnorm[L_W * 37];
    __shared__ __align__(16) float wlr[L_W * R_REG];  // plain [l][36]
    __shared__ __align__(16) float xs[L_W * NBLK];
    __shared__ float ssc[L_W];
    __shared__ __align__(16) float qsh[L_W * NBLK];
    __shared__ float red[16];

    for (int i = t; i < 1024; i += 512) qsh[i] = g_qns[c * 1024 + i];
    if (t < L_W) ssc[t] = g_scap[c * L_W + t];

    // phase 1 (coalesced): warp = region, lane = word
    #pragma unroll
    for (int p = 0; p < 3; p++) {
        int r = warp + p * 16;
        if (r < R_REG) {
            float a = g_attn[((size_t)(b * R_REG + r)) * (C_CAP * L_W) + c * L_W + lane];
            a = (a >= 0.f) ? a : 0.1f * a;
            float ss = a * a;
            #pragma unroll
            for (int o = 16; o; o >>= 1) ss += __shfl_xor_sync(0xffffffffu, ss, o);
            tnorm[lane * 37 + r] = a * (1.f / (sqrtf(ss) + 1e-8f));
        }
    }
    __syncthreads();
    // softmax over regions per word
    if (t < L_W) {
        float m = -1e30f;
        #pragma unroll
        for (int r = 0; r < R_REG; r++) m = fmaxf(m, tnorm[t * 37 + r]);
        float s = 0.f;
        float e[R_REG];
        #pragma unroll
        for (int r = 0; r < R_REG; r++) {
            e[r] = expf(LAM * (tnorm[t * 37 + r] - m));
            s += e[r];
        }
        float inv = 1.f / s;
        #pragma unroll
        for (int r = 0; r < R_REG; r++) wlr[t * R_REG + r] = e[r] * inv;
    }
    __syncthreads();

    // phase 2+3: warp owns blocks (warp, warp+16); lane = element in block
    // natural pairs: colp[i] = (img[2i][e], img[2i+1][e]) pairs with (w_2i, w_2i+1)
    int e0 = warp * 32 + lane;
    int e1 = e0 + 512;
    const float* imgb = imgs + (size_t)b * R_REG * E_DIM;
    const float* capc = caps + (size_t)c * L_W * E_DIM;
    ull colp0[18], colp1[18];
    #pragma unroll
    for (int i = 0; i < 18; i++) {
        float v0a = imgb[(2 * i) * E_DIM + e0];
        float v0b = imgb[(2 * i + 1) * E_DIM + e0];
        PK2(colp0[i], v0a, v0b);
        float v1a = imgb[(2 * i) * E_DIM + e1];
        float v1b = imgb[(2 * i + 1) * E_DIM + e1];
        PK2(colp1[i], v1a, v1b);
    }
    float q0n = capc[e0];
    float q1n = capc[e1];
    #pragma unroll 2
    for (int l = 0; l < L_W; l++) {
        float q0 = q0n, q1 = q1n;
        if (l < L_W - 1) {
            q0n = capc[(l + 1) * E_DIM + e0];
            q1n = capc[(l + 1) * E_DIM + e1];
        }
        const ulonglong2* wp = (const ulonglong2*)(wlr + l * R_REG);
        ull a00 = 0ULL, a01 = 0ULL, a10 = 0ULL, a11 = 0ULL;
        #pragma unroll
        for (int i = 0; i < 9; i++) {
            ulonglong2 wq = wp[i];
            FFMA2(a00, wq.x, colp0[2 * i + 0], a00);
            FFMA2(a01, wq.y, colp0[2 * i + 1], a01);
            FFMA2(a10, wq.x, colp1[2 * i + 0], a10);
            FFMA2(a11, wq.y, colp1[2 * i + 1], a11);
        }
        ull s0; FADD2(s0, a00, a01);
        ull s1; FADD2(s1, a10, a11);
        float w0a, w0b; UPK2(w0a, w0b, s0);
        float w1a, w1b; UPK2(w1a, w1b, s1);
        float w0 = w0a + w0b;
        float w1 = w1a + w1b;
        float n0 = q0 * w0, c0 = w0 * w0;
        float n1 = q1 * w1, c1 = w1 * w1;
        // folded reduction: 4 values -> 7 shfl
        bool hi16 = (lane & 16) != 0;
        float van = hi16 ? n1 : n0, oan = hi16 ? n0 : n1;
        float rn = van + __shfl_xor_sync(0xffffffffu, oan, 16);
        float vac = hi16 ? c1 : c0, oac = hi16 ? c0 : c1;
        float rc = vac + __shfl_xor_sync(0xffffffffu, oac, 16);
        bool hi8 = (lane & 8) != 0;
        float vb = hi8 ? rc : rn, ob = hi8 ? rn : rc;
        float r = vb + __shfl_xor_sync(0xffffffffu, ob, 8);
        r += __shfl_xor_sync(0xffffffffu, r, 4);
        r += __shfl_xor_sync(0xffffffffu, r, 2);
        r += __shfl_xor_sync(0xffffffffu, r, 1);
        // lane0=n0, lane8=c0, lane16=n1, lane24=c1
        float cpart = __shfl_sync(0xffffffffu, r, (lane & 16) | 8);
        if ((lane & 15) == 0) {
            int kblk = warp + (lane & 16);
            float den = fmaxf(qsh[l * 32 + kblk] * sqrtf(cpart), 1e-8f);
            xs[l * NBLK + kblk] = (r / den) * ssc[l];
        }
    }
    __syncthreads();

    // write x to gmem
    if (t < 256) {
        float4* xo4 = (float4*)(g_x + (size_t)(c * B_IMG + b) * (L_W * NBLK));
        xo4[t] = ((const float4*)xs)[t];
    }

    // phase 4: sim = mean_l( tanh(x @ W1c^T + b1) @ W2 ) + b2
    ull w1p[16];
    {
        float wr[NBLK];
        #pragma unroll
        for (int k = 0; k < NBLK; k++) wr[k] = g_W1c[k * HID + t];
        #pragma unroll
        for (int j = 0; j < 16; j++) PK2(w1p[j], wr[2 * j], wr[2 * j + 1]);
    }
    float bb1 = b1[t];
    float w2 = W2[t];
    float acc = 0.f;
    #pragma unroll 4
    for (int l = 0; l < L_W; l++) {
        const ulonglong2* x4 = (const ulonglong2*)(xs + l * NBLK);
        ull d2; PK2(d2, bb1, 0.f);
        #pragma unroll
        for (int j = 0; j < 8; j++) {
            ulonglong2 xq = x4[j];
            FFMA2(d2, xq.x, w1p[2 * j + 0], d2);
            FFMA2(d2, xq.y, w1p[2 * j + 1], d2);
        }
        float dlo, dhi; UPK2(dlo, dhi, d2);
        float th; TANH_APX(th, dlo + dhi);
        acc = fmaf(th, w2, acc);
    }
    #pragma unroll
    for (int o = 16; o; o >>= 1) acc += __shfl_down_sync(0xffffffffu, acc, o);
    if (lane == 0) red[warp] = acc;
    __syncthreads();
    if (t == 0) {
        float s = 0.f;
        #pragma unroll
        for (int i = 0; i < 16; i++) s += red[i];
        out_sim[b * C_CAP + c] = s * (1.f / 32.f) + b2[0];
    }
}

// ---------------- kernel D: softmax over captions ----------------
__global__ void k_softmax(const float* __restrict__ sims) {
    int b = blockIdx.x;
    int t = threadIdx.x;  // 64
    __shared__ float sh[64];
    __shared__ float mx, sm;
    float v = sims[b * C_CAP + t];
    sh[t] = v;
    __syncthreads();
    if (t == 0) {
        float m = sh[0];
        for (int i = 1; i < 64; i++) m = fmaxf(m, sh[i]);
        mx = m;
    }
    __syncthreads();
    float e = expf(v - mx);
    sh[t] = e;
    __syncthreads();
    if (t == 0) {
        float s = 0.f;
        for (int i = 0; i < 64; i++) s += sh[i];
        sm = s;
    }
    __syncthreads();
    g_w[b * C_CAP + t] = e / sm;
}

// ---------------- kernel E: weighted Gaussian moments, (dm,dl) packed ----------------
__global__ void __launch_bounds__(512) k_moments(const float* __restrict__ bmu,
                                                 const float* __restrict__ blv,
                                                 float* __restrict__ out) {
    int bl = blockIdx.x;        // b*32 + l
    int b = bl >> 5, l = bl & 31;
    int t = threadIdx.x;        // 512 (h)
    __shared__ __align__(16) float xsh[C_CAP * NBLK];
    __shared__ float wsh[C_CAP];
    for (int i = t; i < C_CAP * NBLK / 4; i += 512) {
        int c = i >> 3, k4 = i & 7;
        ((float4*)xsh)[i] = *(const float4*)(g_x + (size_t)(c * B_IMG + b) * (L_W * NBLK) + l * NBLK + k4 * 4);
    }
    if (t < C_CAP) wsh[t] = g_w[b * C_CAP + t];
    __syncthreads();

    ull wml[NBLK];
    #pragma unroll
    for (int k = 0; k < NBLK; k++)
        wml[k] = *(const ull*)&g_Wml[k * HID + t];   // (wmu, wlv)
    ull bias2; PK2(bias2, bmu[t], blv[t]);
    float am = 0.f, ae = 0.f;
    #pragma unroll 2
    for (int c = 0; c < C_CAP; c++) {
        const float4* xr4 = (const float4*)(xsh + c * NBLK);
        ull d2 = bias2;
        #pragma unroll
        for (int k4 = 0; k4 < 8; k4++) {
            float4 xv = xr4[k4];
            ull x0, x1, x2, x3;
            PK2(x0, xv.x, xv.x); PK2(x1, xv.y, xv.y);
            PK2(x2, xv.z, xv.z); PK2(x3, xv.w, xv.w);
            FFMA2(d2, x0, wml[k4 * 4 + 0], d2);
            FFMA2(d2, x1, wml[k4 * 4 + 1], d2);
            FFMA2(d2, x2, wml[k4 * 4 + 2], d2);
            FFMA2(d2, x3, wml[k4 * 4 + 3], d2);
        }
        float dm, dl; UPK2(dm, dl, d2);
        float w = wsh[c];
        am = fmaf(w, dm, am);
        ae = fmaf(w, expf(dl) + dm * dm, ae);
    }
    float var = ae - am * am;
    float sg = sqrtf(fmaxf(var, 1e-8f));
    size_t o = (size_t)bl * HID + t;
    out[4096 + o] = am;
    out[4096 + (size_t)B_IMG * L_W * HID + o] = sg;
}

// ---------------- launch ----------------
extern "C" void kernel_launch(void* const* d_in, const int* in_sizes, int n_in,
                              void* d_out, int out_size) {
    const float* images   = (const float*)d_in[0];
    const float* captions = (const float*)d_in[1];
    const int*   depends  = (const int*)d_in[2];
    const float* W_gc     = (const float*)d_in[3];
    const float* W_mu     = (const float*)d_in[4];
    const float* b_mu     = (const float*)d_in[5];
    const float* W_lv     = (const float*)d_in[6];
    const float* b_lv     = (const float*)d_in[7];
    const float* W1       = (const float*)d_in[8];
    const float* b1       = (const float*)d_in[9];
    const float* W2       = (const float*)d_in[10];
    const float* b2       = (const float*)d_in[11];
    float* out = (float*)d_out;

    static bool attr_set = false;
    if (!attr_set) {
        cudaFuncSetAttribute(k_caption, cudaFuncAttributeMaxDynamicSharedMemorySize,
                             A_SMEM_FLOATS * sizeof(float));
        attr_set = true;
    }

    float* attn_ptr;
    cudaGetSymbolAddress((void**)&attn_ptr, g_attn);

    k_compose<<<dim3(HID, 3), 32>>>(W_gc, W_mu, W_lv, W1);
    k_caption<<<C_CAP, 256, A_SMEM_FLOATS * sizeof(float)>>>(captions, depends);
    k_gemm_nt<<<dim3(16, 18), 256>>>(images, captions, attn_ptr);
    k_fused<<<dim3(C_CAP, B_IMG), 512>>>(images, captions, b1, W2, b2, out);
    k_softmax<<<B_IMG, 64>>>(out);
    k_moments<<<B_IMG * L_W, 512>>>(b_mu, b_lv, out);
}

// round 7
// speedup vs baseline: 2.0507x; 1.0408x over previous
#include <cuda_runtime.h>
#include <math.h>
#include <stdint.h>

// ---------------- dims ----------------
#define B_IMG 64
#define R_REG 36
#define E_DIM 1024
#define C_CAP 64
#define L_W   32
#define N_DEP 30
#define NBLK  32
#define BLK   32
#define HID   512
#define LAM   9.0f

typedef unsigned long long ull;

// f32x2 packed helpers (sm_100+ PTX)
#define PK2(d, lo, hi)   asm("mov.b64 %0, {%1, %2};" : "=l"(d) : "f"(lo), "f"(hi))
#define UPK2(lo, hi, s)  asm("mov.b64 {%0, %1}, %2;" : "=f"(lo), "=f"(hi) : "l"(s))
#define FFMA2(d, a, b, c) asm("fma.rn.f32x2 %0, %1, %2, %3;" : "=l"(d) : "l"(a), "l"(b), "l"(c))
#define FADD2(d, a, b)    asm("add.rn.f32x2 %0, %1, %2;" : "=l"(d) : "l"(a), "l"(b))
#define TANH_APX(d, a)    asm("tanh.approx.f32 %0, %1;" : "=f"(d) : "f"(a))

// ---------------- scratch ----------------
__device__ float g_attn[(size_t)B_IMG * R_REG * C_CAP * L_W];
__device__ float g_scap[C_CAP * L_W];
__device__ float g_qns[C_CAP * L_W * NBLK];
__device__ float g_x[(size_t)C_CAP * B_IMG * L_W * NBLK];
__device__ float g_w[B_IMG * C_CAP];
__device__ float2 g_Wml[NBLK * HID];            // [k][h] -> (wmu, wlv)
__device__ float g_W1c[NBLK * HID];             // transposed [k][h]

// ---------------- compose W @ W_gc ----------------
__global__ void k_compose(const float* __restrict__ Wgc,
                          const float* __restrict__ Wmu,
                          const float* __restrict__ Wlv,
                          const float* __restrict__ W1) {
    int h = blockIdx.x;
    int m = blockIdx.y;
    int k = threadIdx.x;  // 0..31
    const float* W = (m == 0) ? Wmu : (m == 1) ? Wlv : W1;
    float acc = 0.f;
    #pragma unroll 8
    for (int j = 0; j < HID; j++)
        acc += W[h * HID + j] * Wgc[j * NBLK + k];
    if (m == 0)      g_Wml[k * HID + h].x = acc;
    else if (m == 1) g_Wml[k * HID + h].y = acc;
    else             g_W1c[k * HID + h] = acc;
}

// ---------------- kernel A: per-caption s[l] + block norms ----------------
#define A_SMEM_FLOATS (32 * 1025 + 1024 + 1024)
__global__ void k_caption(const float* __restrict__ caps,
                          const int* __restrict__ deps) {
    int c = blockIdx.x;
    int t = threadIdx.x;  // 256
    extern __shared__ float sh[];
    float* cs  = sh;                  // [32][1025]
    float* G   = cs + 32 * 1025;
    float* adj = G + 1024;

    const float* cp = caps + (size_t)c * L_W * E_DIM;
    for (int i = t; i < L_W * E_DIM; i += 256) {
        int l = i >> 10, e = i & 1023;
        cs[l * 1025 + e] = cp[i];
    }
    __syncthreads();

    for (int p = t; p < 1024; p += 256) {
        int l = p >> 5, k = p & 31;
        float s = 0.f;
        #pragma unroll
        for (int j = 0; j < 32; j++) {
            float v = cs[l * 1025 + k * 32 + j];
            s += v * v;
        }
        g_qns[c * 1024 + p] = sqrtf(s);
    }

    for (int p = t; p < 1024; p += 256) {
        int i = p >> 5, j = p & 31;
        float acc = 0.f;
        #pragma unroll 8
        for (int e = 0; e < E_DIM; e++)
            acc += cs[i * 1025 + e] * cs[j * 1025 + e];
        G[p] = acc;
    }
    __syncthreads();

    if (t < 32) {
        float m = -1e30f;
        for (int j = 0; j < 32; j++) m = fmaxf(m, G[t * 32 + j]);
        float s = 0.f;
        for (int j = 0; j < 32; j++) {
            float e = expf(LAM * (G[t * 32 + j] - m));
            G[t * 32 + j] = e;
            s += e;
        }
        float inv = 1.f / s;
        for (int j = 0; j < 32; j++) G[t * 32 + j] *= inv;
    }
    for (int p = t; p < 1024; p += 256) adj[p] = 0.f;
    __syncthreads();
    if (t == 0) {
        for (int i = 1; i < N_DEP; i++) {
            int a = deps[c * (N_DEP * 2) + i * 2 + 0];
            int b = deps[c * (N_DEP * 2) + i * 2 + 1];
            adj[a * 32 + b] = 1.f;
            adj[b * 32 + a] = 1.f;
        }
        for (int i = 0; i < 32; i++) adj[i * 32 + i] += 1.f;
    }
    __syncthreads();
    if (t < 32) {
        float ss = 0.f;
        for (int j = 0; j < 32; j++) {
            float m2 = adj[t * 32 + j] * G[t * 32 + j];
            ss += m2 * m2;
        }
        float inv = 1.f / (sqrtf(ss) + 1e-8f);
        float s = 0.f;
        for (int j = 0; j < 32; j++) {
            float a = adj[t * 32 + j];
            s += a * G[t * 32 + j] * inv * a;
        }
        g_scap[c * 32 + t] = s;
    }
}

// ---------------- kernel B: logits GEMM, f32x2 packed ----------------
__global__ void __launch_bounds__(256) k_gemm_nt(const float* __restrict__ A,
                                                 const float* __restrict__ B,
                                                 float* __restrict__ C) {
    __shared__ __align__(16) float As[2][8][132];
    __shared__ __align__(16) float Bs[2][8][132];
    int tm = blockIdx.y, tn = blockIdx.x;
    int t = threadIdx.x;
    int ty = t >> 4, tx = t & 15;
    int lr = t >> 1;
    int lk = (t & 1) * 4;
    const float* Ab = A + (size_t)(tm * 128 + lr) * E_DIM + lk;
    const float* Bb = B + (size_t)(tn * 128 + lr) * E_DIM + lk;
    ull acc[8][4];
    #pragma unroll
    for (int i = 0; i < 8; i++)
        #pragma unroll
        for (int j = 0; j < 4; j++) acc[i][j] = 0ULL;

    float4 av = *(const float4*)(Ab);
    float4 bv = *(const float4*)(Bb);
    As[0][lk + 0][lr] = av.x; As[0][lk + 1][lr] = av.y;
    As[0][lk + 2][lr] = av.z; As[0][lk + 3][lr] = av.w;
    Bs[0][lk + 0][lr] = bv.x; Bs[0][lk + 1][lr] = bv.y;
    Bs[0][lk + 2][lr] = bv.z; Bs[0][lk + 3][lr] = bv.w;
    __syncthreads();

    int p = 0;
    for (int k0 = 0; k0 < E_DIM; k0 += 8) {
        if (k0 + 8 < E_DIM) {
            av = *(const float4*)(Ab + k0 + 8);
            bv = *(const float4*)(Bb + k0 + 8);
        }
        #pragma unroll
        for (int k = 0; k < 8; k++) {
            float4 a0 = *(const float4*)&As[p][k][ty * 4];
            float4 a1 = *(const float4*)&As[p][k][64 + ty * 4];
            ulonglong2 bq0 = *(const ulonglong2*)&Bs[p][k][tx * 4];
            ulonglong2 bq1 = *(const ulonglong2*)&Bs[p][k][64 + tx * 4];
            float a_[8] = {a0.x, a0.y, a0.z, a0.w, a1.x, a1.y, a1.z, a1.w};
            #pragma unroll
            for (int i = 0; i < 8; i++) {
                ull ai2; PK2(ai2, a_[i], a_[i]);
                FFMA2(acc[i][0], ai2, bq0.x, acc[i][0]);
                FFMA2(acc[i][1], ai2, bq0.y, acc[i][1]);
                FFMA2(acc[i][2], ai2, bq1.x, acc[i][2]);
                FFMA2(acc[i][3], ai2, bq1.y, acc[i][3]);
            }
        }
        if (k0 + 8 < E_DIM) {
            int q = p ^ 1;
            As[q][lk + 0][lr] = av.x; As[q][lk + 1][lr] = av.y;
            As[q][lk + 2][lr] = av.z; As[q][lk + 3][lr] = av.w;
            Bs[q][lk + 0][lr] = bv.x; Bs[q][lk + 1][lr] = bv.y;
            Bs[q][lk + 2][lr] = bv.z; Bs[q][lk + 3][lr] = bv.w;
            __syncthreads();
            p = q;
        }
    }
    const int N = C_CAP * L_W;
    #pragma unroll
    for (int i = 0; i < 8; i++) {
        int row = tm * 128 + ((i < 4) ? (ty * 4 + i) : (64 + ty * 4 + (i - 4)));
        float c0, c1, c2, c3, c4, c5, c6, c7;
        UPK2(c0, c1, acc[i][0]); UPK2(c2, c3, acc[i][1]);
        UPK2(c4, c5, acc[i][2]); UPK2(c6, c7, acc[i][3]);
        *(float4*)(C + (size_t)row * N + tn * 128 + tx * 4) = make_float4(c0, c1, c2, c3);
        *(float4*)(C + (size_t)row * N + tn * 128 + 64 + tx * 4) = make_float4(c4, c5, c6, c7);
    }
}

// ---------------- kernel C: fused per-(c,b), 4-shfl folded reductions ----------------
__global__ void __launch_bounds__(512) k_fused(const float* __restrict__ imgs,
                                               const float* __restrict__ caps,
                                               const float* __restrict__ b1,
                                               const float* __restrict__ W2,
                                               const float* __restrict__ b2,
                                               float* __restrict__ out_sim) {
    int c = blockIdx.x;
    int b = blockIdx.y;
    int t = threadIdx.x;  // 512 = 16 warps
    int warp = t >> 5, lane = t & 31;
    __shared__ __align__(16) float tnorm[L_W * 37];
    __shared__ __align__(16) float wlr[L_W * R_REG];  // [l][36]
    __shared__ __align__(16) float xs[L_W * NBLK];
    __shared__ __align__(16) float xn[L_W * NBLK];    // numerator partials
    __shared__ __align__(16) float xc[L_W * NBLK];    // wctx-norm^2 partials
    __shared__ float ssc[L_W];
    __shared__ __align__(16) float qsh[L_W * NBLK];
    __shared__ float red[16];

    for (int i = t; i < 1024; i += 512) qsh[i] = g_qns[c * 1024 + i];
    if (t < L_W) ssc[t] = g_scap[c * L_W + t];

    // phase 1 (coalesced): warp = region, lane = word
    #pragma unroll
    for (int p = 0; p < 3; p++) {
        int r = warp + p * 16;
        if (r < R_REG) {
            float a = g_attn[((size_t)(b * R_REG + r)) * (C_CAP * L_W) + c * L_W + lane];
            a = (a >= 0.f) ? a : 0.1f * a;
            float ss = a * a;
            #pragma unroll
            for (int o = 16; o; o >>= 1) ss += __shfl_xor_sync(0xffffffffu, ss, o);
            tnorm[lane * 37 + r] = a * (1.f / (sqrtf(ss) + 1e-8f));
        }
    }
    __syncthreads();
    // softmax over regions per word
    if (t < L_W) {
        float m = -1e30f;
        #pragma unroll
        for (int r = 0; r < R_REG; r++) m = fmaxf(m, tnorm[t * 37 + r]);
        float s = 0.f;
        float e[R_REG];
        #pragma unroll
        for (int r = 0; r < R_REG; r++) {
            e[r] = expf(LAM * (tnorm[t * 37 + r] - m));
            s += e[r];
        }
        float inv = 1.f / s;
        #pragma unroll
        for (int r = 0; r < R_REG; r++) wlr[t * R_REG + r] = e[r] * inv;
    }
    __syncthreads();

    // phase 2+3: 16-lane group owns one block; lane gl owns elements gl, gl+16
    int group = lane >> 4;            // 0 or 1
    int gl = lane & 15;
    int kblk = warp + 16 * group;     // block index 0..31
    int ea = kblk * 32 + gl;
    int eb = ea + 16;
    const float* imgb = imgs + (size_t)b * R_REG * E_DIM;
    const float* capc = caps + (size_t)c * L_W * E_DIM;
    ull cpa[18], cpb[18];             // natural-r pairs (img[2i][e], img[2i+1][e])
    #pragma unroll
    for (int i = 0; i < 18; i++) {
        float va0 = imgb[(2 * i) * E_DIM + ea];
        float va1 = imgb[(2 * i + 1) * E_DIM + ea];
        PK2(cpa[i], va0, va1);
        float vb0 = imgb[(2 * i) * E_DIM + eb];
        float vb1 = imgb[(2 * i + 1) * E_DIM + eb];
        PK2(cpb[i], vb0, vb1);
    }
    float qan = capc[ea];
    float qbn = capc[eb];
    bool hi8 = (gl & 8) != 0;
    #pragma unroll 2
    for (int l = 0; l < L_W; l++) {
        float qa = qan, qb = qbn;
        if (l < L_W - 1) {
            qan = capc[(l + 1) * E_DIM + ea];
            qbn = capc[(l + 1) * E_DIM + eb];
        }
        const ulonglong2* wp = (const ulonglong2*)(wlr + l * R_REG);
        ull aa0 = 0ULL, aa1 = 0ULL, ab0 = 0ULL, ab1 = 0ULL;
        #pragma unroll
        for (int i = 0; i < 9; i++) {
            ulonglong2 wq = wp[i];
            FFMA2(aa0, wq.x, cpa[2 * i + 0], aa0);
            FFMA2(aa1, wq.y, cpa[2 * i + 1], aa1);
            FFMA2(ab0, wq.x, cpb[2 * i + 0], ab0);
            FFMA2(ab1, wq.y, cpb[2 * i + 1], ab1);
        }
        ull sa; FADD2(sa, aa0, aa1);
        ull sb; FADD2(sb, ab0, ab1);
        float wa0, wa1; UPK2(wa0, wa1, sa);
        float wb0, wb1; UPK2(wb0, wb1, sb);
        float wa = wa0 + wa1;
        float wb = wb0 + wb1;
        float n = qa * wa + qb * wb;
        float cc = wa * wa + wb * wb;
        // folded 16-lane reduction: 4 shfls; n-sum -> gl==0, cc-sum -> gl==8
        float v = hi8 ? cc : n;
        float o = hi8 ? n : cc;
        v += __shfl_xor_sync(0xffffffffu, o, 8);
        v += __shfl_xor_sync(0xffffffffu, v, 4);
        v += __shfl_xor_sync(0xffffffffu, v, 2);
        v += __shfl_xor_sync(0xffffffffu, v, 1);
        if ((gl & 7) == 0) {
            if (hi8) xc[l * NBLK + kblk] = v;
            else     xn[l * NBLK + kblk] = v;
        }
    }
    __syncthreads();

    // phase 3.5: combine partials -> xs, write g_x (coalesced)
    {
        float* xg = g_x + (size_t)(c * B_IMG + b) * (L_W * NBLK);
        #pragma unroll
        for (int p = t; p < L_W * NBLK; p += 512) {
            int l = p >> 5;
            float den = fmaxf(qsh[p] * sqrtf(xc[p]), 1e-8f);
            float x = (xn[p] / den) * ssc[l];
            xs[p] = x;
            xg[p] = x;
        }
    }
    __syncthreads();

    // phase 4: sim = mean_l( tanh(x @ W1c^T + b1) @ W2 ) + b2
    ull w1p[16];
    {
        float wr[NBLK];
        #pragma unroll
        for (int k = 0; k < NBLK; k++) wr[k] = g_W1c[k * HID + t];
        #pragma unroll
        for (int j = 0; j < 16; j++) PK2(w1p[j], wr[2 * j], wr[2 * j + 1]);
    }
    float bb1 = b1[t];
    float w2 = W2[t];
    float acc = 0.f;
    #pragma unroll 4
    for (int l = 0; l < L_W; l++) {
        const ulonglong2* x4 = (const ulonglong2*)(xs + l * NBLK);
        ull d2; PK2(d2, bb1, 0.f);
        #pragma unroll
        for (int j = 0; j < 8; j++) {
            ulonglong2 xq = x4[j];
            FFMA2(d2, xq.x, w1p[2 * j + 0], d2);
            FFMA2(d2, xq.y, w1p[2 * j + 1], d2);
        }
        float dlo, dhi; UPK2(dlo, dhi, d2);
        float th; TANH_APX(th, dlo + dhi);
        acc = fmaf(th, w2, acc);
    }
    #pragma unroll
    for (int o = 16; o; o >>= 1) acc += __shfl_down_sync(0xffffffffu, acc, o);
    if (lane == 0) red[warp] = acc;
    __syncthreads();
    if (t == 0) {
        float s = 0.f;
        #pragma unroll
        for (int i = 0; i < 16; i++) s += red[i];
        out_sim[b * C_CAP + c] = s * (1.f / 32.f) + b2[0];
    }
}

// ---------------- kernel D: softmax over captions ----------------
__global__ void k_softmax(const float* __restrict__ sims) {
    int b = blockIdx.x;
    int t = threadIdx.x;  // 64
    __shared__ float sh[64];
    __shared__ float mx, sm;
    float v = sims[b * C_CAP + t];
    sh[t] = v;
    __syncthreads();
    if (t == 0) {
        float m = sh[0];
        for (int i = 1; i < 64; i++) m = fmaxf(m, sh[i]);
        mx = m;
    }
    __syncthreads();
    float e = expf(v - mx);
    sh[t] = e;
    __syncthreads();
    if (t == 0) {
        float s = 0.f;
        for (int i = 0; i < 64; i++) s += sh[i];
        sm = s;
    }
    __syncthreads();
    g_w[b * C_CAP + t] = e / sm;
}

// ---------------- kernel E: weighted Gaussian moments, (dm,dl) packed ----------------
__global__ void __launch_bounds__(512) k_moments(const float* __restrict__ bmu,
                                                 const float* __restrict__ blv,
                                                 float* __restrict__ out) {
    int bl = blockIdx.x;        // b*32 + l
    int b = bl >> 5, l = bl & 31;
    int t = threadIdx.x;        // 512 (h)
    __shared__ __align__(16) float xsh[C_CAP * NBLK];
    __shared__ float wsh[C_CAP];
    for (int i = t; i < C_CAP * NBLK / 4; i += 512) {
        int c = i >> 3, k4 = i & 7;
        ((float4*)xsh)[i] = *(const float4*)(g_x + (size_t)(c * B_IMG + b) * (L_W * NBLK) + l * NBLK + k4 * 4);
    }
    if (t < C_CAP) wsh[t] = g_w[b * C_CAP + t];
    __syncthreads();

    ull wml[NBLK];
    #pragma unroll
    for (int k = 0; k < NBLK; k++)
        wml[k] = *(const ull*)&g_Wml[k * HID + t];   // (wmu, wlv)
    ull bias2; PK2(bias2, bmu[t], blv[t]);
    float am = 0.f, ae = 0.f;
    #pragma unroll 2
    for (int c = 0; c < C_CAP; c++) {
        const float4* xr4 = (const float4*)(xsh + c * NBLK);
        ull d2 = bias2;
        #pragma unroll
        for (int k4 = 0; k4 < 8; k4++) {
            float4 xv = xr4[k4];
            ull x0, x1, x2, x3;
            PK2(x0, xv.x, xv.x); PK2(x1, xv.y, xv.y);
            PK2(x2, xv.z, xv.z); PK2(x3, xv.w, xv.w);
            FFMA2(d2, x0, wml[k4 * 4 + 0], d2);
            FFMA2(d2, x1, wml[k4 * 4 + 1], d2);
            FFMA2(d2, x2, wml[k4 * 4 + 2], d2);
            FFMA2(d2, x3, wml[k4 * 4 + 3], d2);
        }
        float dm, dl; UPK2(dm, dl, d2);
        float w = wsh[c];
        am = fmaf(w, dm, am);
        ae = fmaf(w, expf(dl) + dm * dm, ae);
    }
    float var = ae - am * am;
    float sg = sqrtf(fmaxf(var, 1e-8f));
    size_t o = (size_t)bl * HID + t;
    out[4096 + o] = am;
    out[4096 + (size_t)B_IMG * L_W * HID + o] = sg;
}

// ---------------- launch ----------------
extern "C" void kernel_launch(void* const* d_in, const int* in_sizes, int n_in,
                              void* d_out, int out_size) {
    const float* images   = (const float*)d_in[0];
    const float* captions = (const float*)d_in[1];
    const int*   depends  = (const int*)d_in[2];
    const float* W_gc     = (const float*)d_in[3];
    const float* W_mu     = (const float*)d_in[4];
    const float* b_mu     = (const float*)d_in[5];
    const float* W_lv     = (const float*)d_in[6];
    const float* b_lv     = (const float*)d_in[7];
    const float* W1       = (const float*)d_in[8];
    const float* b1       = (const float*)d_in[9];
    const float* W2       = (const float*)d_in[10];
    const float* b2       = (const float*)d_in[11];
    float* out = (float*)d_out;

    static bool attr_set = false;
    if (!attr_set) {
        cudaFuncSetAttribute(k_caption, cudaFuncAttributeMaxDynamicSharedMemorySize,
                             A_SMEM_FLOATS * sizeof(float));
        attr_set = true;
    }

    float* attn_ptr;
    cudaGetSymbolAddress((void**)&attn_ptr, g_attn);

    k_compose<<<dim3(HID, 3), 32>>>(W_gc, W_mu, W_lv, W1);
    k_caption<<<C_CAP, 256, A_SMEM_FLOATS * sizeof(float)>>>(captions, depends);
    k_gemm_nt<<<dim3(16, 18), 256>>>(images, captions, attn_ptr);
    k_fused<<<dim3(C_CAP, B_IMG), 512>>>(images, captions, b1, W2, b2, out);
    k_softmax<<<B_IMG, 64>>>(out);
    k_moments<<<B_IMG * L_W, 512>>>(b_mu, b_lv, out);
}